// round 6
// baseline (speedup 1.0000x reference)
#include <cuda_runtime.h>
#include <math.h>

#define HEADS 8
#define DHEAD 40
#define CMODEL 320
#define CX 768
#define LSEQ 77
#define NB 10          // attention batches
#define HW 4096
#define NPHASE 9
#define AT_ROWS 64

// ---------------- scratch (device globals; no allocation allowed) ----------
__device__ __align__(16) float g_q[2 * HW * CMODEL];        // 2 distinct q batches
__device__ __align__(16) float g_k[NB * LSEQ * CMODEL];
__device__ __align__(16) float g_v[NB * LSEQ * CMODEL];
__device__ __align__(16) float g_A[2 * HW * CMODEL];        // [0:HW)=A0 (batch0), [HW:2HW)=weighted sum
__device__ __align__(16) float g_w9[NPHASE * HW];
__device__ __align__(16) float g_wsum[HW];

// ---------------- phase-weight kernel (jax.image.resize bilinear+antialias) -
__device__ __forceinline__ float resize_factor(int o, float lo, float hi) {
    // output pixel o of a 512->64 resize of the indicator [lo, hi) on rows.
    // triangle kernel scaled by 8 (antialias), normalized over in-range taps.
    float sf = (o + 0.5f) * 8.0f - 0.5f;
    float num = 0.f, den = 0.f;
    int h0 = o * 8 - 4, h1 = o * 8 + 11;
    #pragma unroll 1
    for (int h = h0; h <= h1; ++h) {
        if (h < 0 || h > 511) continue;
        float fh = (float)h;
        float wgt = 1.0f - fabsf(fh - sf) * 0.125f;
        den += wgt;
        if (fh >= lo && fh < hi) num += wgt;
    }
    return num / den;
}

__global__ void weights_kernel(const float* __restrict__ bboxes) {
    int p = blockIdx.x * blockDim.x + threadIdx.x;
    if (p >= HW) return;
    int r = p >> 6, c = p & 63;
    float s = 0.1f;
    g_w9[p] = 0.1f;                 // phase 0 (plain uncond-text batch)
    #pragma unroll 1
    for (int i = 0; i < 8; ++i) {
        float x0 = bboxes[i * 4 + 0], y0 = bboxes[i * 4 + 1];
        float x1 = bboxes[i * 4 + 2], y1 = bboxes[i * 4 + 3];
        float wmin = floorf(512.f * x0), wmax = floorf(512.f * x1);
        float hmin = floorf(512.f * y0), hmax = floorf(512.f * y1);
        float wv = 10.f * resize_factor(r, hmin, hmax) * resize_factor(c, wmin, wmax);
        g_w9[(i + 1) * HW + p] = wv;
        s += wv;
    }
    g_wsum[p] = s;
}

// ---------------- tiled fp32 GEMM core: 64x64 tile, BK=16, 256 threads -----
__device__ __forceinline__ void gemm_tile(
    const float* __restrict__ A, const float* __restrict__ B,
    int M, int K, float (&acc)[4][4], int N)
{
    __shared__ __align__(16) float As[16][72];   // [k][row], padded (72*4B mult of 16)
    __shared__ __align__(16) float Bs[16][64];   // [k][col]
    int tx = threadIdx.x, ty = threadIdx.y;
    int t  = ty * 16 + tx;
    int row0 = blockIdx.y * 64, col0 = blockIdx.x * 64;
    int li = t >> 2, lk = (t & 3) << 2;          // A loader: row li, k-quad lk
    int bk = t >> 4, bj = (t & 15) << 2;         // B loader: k-row bk, col-quad bj

    #pragma unroll
    for (int i = 0; i < 4; ++i)
        #pragma unroll
        for (int j = 0; j < 4; ++j) acc[i][j] = 0.f;

    for (int k0 = 0; k0 < K; k0 += 16) {
        float4 av = make_float4(0.f, 0.f, 0.f, 0.f);
        int ar = row0 + li;
        if (ar < M) av = *(const float4*)(A + (size_t)ar * K + k0 + lk);
        As[lk + 0][li] = av.x; As[lk + 1][li] = av.y;
        As[lk + 2][li] = av.z; As[lk + 3][li] = av.w;
        *(float4*)(&Bs[bk][bj]) = *(const float4*)(B + (size_t)(k0 + bk) * N + col0 + bj);
        __syncthreads();
        #pragma unroll
        for (int kk = 0; kk < 16; ++kk) {
            float4 a = *(const float4*)(&As[kk][ty * 4]);
            float4 b = *(const float4*)(&Bs[kk][tx * 4]);
            acc[0][0] += a.x * b.x; acc[0][1] += a.x * b.y; acc[0][2] += a.x * b.z; acc[0][3] += a.x * b.w;
            acc[1][0] += a.y * b.x; acc[1][1] += a.y * b.y; acc[1][2] += a.y * b.z; acc[1][3] += a.y * b.w;
            acc[2][0] += a.z * b.x; acc[2][1] += a.z * b.y; acc[2][2] += a.z * b.z; acc[2][3] += a.z * b.w;
            acc[3][0] += a.w * b.x; acc[3][1] += a.w * b.y; acc[3][2] += a.w * b.z; acc[3][3] += a.w * b.w;
        }
        __syncthreads();
    }
}

// Q projection: [2*HW, 320] x [320, 320] -> g_q
__global__ void __launch_bounds__(256) qproj_kernel(
    const float* __restrict__ hs, const float* __restrict__ Wq)
{
    float acc[4][4];
    gemm_tile(hs, Wq, 2 * HW, CMODEL, acc, CMODEL);
    int row0 = blockIdx.y * 64, col0 = blockIdx.x * 64;
    int tx = threadIdx.x, ty = threadIdx.y;
    #pragma unroll
    for (int i = 0; i < 4; ++i) {
        int r = row0 + ty * 4 + i;
        float4 o = make_float4(acc[i][0], acc[i][1], acc[i][2], acc[i][3]);
        *(float4*)(g_q + (size_t)r * CMODEL + col0 + tx * 4) = o;
    }
}

// K projection: ehs[0:770, 768] x Wk -> g_k
__global__ void __launch_bounds__(256) kproj_kernel(
    const float* __restrict__ ehs, const float* __restrict__ Wk)
{
    float acc[4][4];
    gemm_tile(ehs, Wk, NB * LSEQ, CX, acc, CMODEL);
    int row0 = blockIdx.y * 64, col0 = blockIdx.x * 64;
    int tx = threadIdx.x, ty = threadIdx.y;
    #pragma unroll
    for (int i = 0; i < 4; ++i) {
        int r = row0 + ty * 4 + i;
        if (r >= NB * LSEQ) continue;
        float4 o = make_float4(acc[i][0], acc[i][1], acc[i][2], acc[i][3]);
        *(float4*)(g_k + (size_t)r * CMODEL + col0 + tx * 4) = o;
    }
}

// V projection
__global__ void __launch_bounds__(256) vproj_kernel(
    const float* __restrict__ ehs, const float* __restrict__ Wv)
{
    float acc[4][4];
    gemm_tile(ehs, Wv, NB * LSEQ, CX, acc, CMODEL);
    int row0 = blockIdx.y * 64, col0 = blockIdx.x * 64;
    int tx = threadIdx.x, ty = threadIdx.y;
    #pragma unroll
    for (int i = 0; i < 4; ++i) {
        int r = row0 + ty * 4 + i;
        if (r >= NB * LSEQ) continue;
        float4 o = make_float4(acc[i][0], acc[i][1], acc[i][2], acc[i][3]);
        *(float4*)(g_v + (size_t)r * CMODEL + col0 + tx * 4) = o;
    }
}

// ---------------- attention: 10 batches fused, phase-weighted accumulate ---
// block = (64 q-rows) x 1 head, 64 threads, each thread owns one q row.
__global__ void __launch_bounds__(64) att_kernel()
{
    __shared__ float ks[LSEQ * DHEAD];
    __shared__ float vs[LSEQ * DHEAD];
    __shared__ float sc[AT_ROWS * LSEQ];   // stride 77 (13 mod 32) -> conflict-free
    const int head = blockIdx.y;
    const int t = threadIdx.x;
    const int p = blockIdx.x * AT_ROWS + t;
    float* mysc = sc + t * LSEQ;
    const float scale = 0.15811388300841897f;   // 1/sqrt(40)

    float qreg[DHEAD];
    float aw[DHEAD];
    #pragma unroll
    for (int d = 0; d < DHEAD; ++d) aw[d] = 0.f;

    for (int b = 0; b < NB; ++b) {
        // stage this batch's K/V head tile (77x40) into smem
        for (int idx = t; idx < LSEQ * DHEAD; idx += AT_ROWS) {
            int j = idx / DHEAD, d = idx - j * DHEAD;
            int g = (b * LSEQ + j) * CMODEL + head * DHEAD + d;
            ks[idx] = g_k[g];
            vs[idx] = g_v[g];
        }
        __syncthreads();

        if (b < 2) {   // b==0: q from hs[0]; b==1..9: q from hs[1] (load once)
            const float* qp = g_q + ((size_t)b * HW + p) * CMODEL + head * DHEAD;
            #pragma unroll
            for (int d = 0; d < DHEAD; ++d) qreg[d] = qp[d];
        }

        // pass 1: scores + rowmax
        float m = -1e30f;
        #pragma unroll 2
        for (int j = 0; j < LSEQ; ++j) {
            const float* kj = ks + j * DHEAD;
            float s0 = 0.f, s1 = 0.f, s2 = 0.f, s3 = 0.f;
            #pragma unroll
            for (int d = 0; d < DHEAD; d += 4) {
                s0 += qreg[d + 0] * kj[d + 0];
                s1 += qreg[d + 1] * kj[d + 1];
                s2 += qreg[d + 2] * kj[d + 2];
                s3 += qreg[d + 3] * kj[d + 3];
            }
            float s = ((s0 + s1) + (s2 + s3)) * scale;
            mysc[j] = s;
            m = fmaxf(m, s);
        }

        // pass 2: softmax + PV
        float acc[DHEAD];
        #pragma unroll
        for (int d = 0; d < DHEAD; ++d) acc[d] = 0.f;
        float l = 0.f;
        #pragma unroll 2
        for (int j = 0; j < LSEQ; ++j) {
            float pe = __expf(mysc[j] - m);
            l += pe;
            const float* vj = vs + j * DHEAD;
            #pragma unroll
            for (int d = 0; d < DHEAD; ++d) acc[d] += pe * vj[d];
        }
        float inv = 1.f / l;

        if (b == 0) {
            float* o = g_A + (size_t)p * CMODEL + head * DHEAD;
            #pragma unroll
            for (int d = 0; d < DHEAD; ++d) o[d] = acc[d] * inv;
        } else {
            // fuse BEFORE the Wo projection (linearity of the phase fusion)
            float wg = g_w9[(b - 1) * HW + p] * inv;
            #pragma unroll
            for (int d = 0; d < DHEAD; ++d) aw[d] += wg * acc[d];
        }
        __syncthreads();   // before next batch overwrites ks/vs
    }
    float* o = g_A + (size_t)(HW + p) * CMODEL + head * DHEAD;
    #pragma unroll
    for (int d = 0; d < DHEAD; ++d) o[d] = aw[d];
}

// ---------------- output projection + fused epilogue -----------------------
// rows [0,HW): out0 = A0@Wo + bo
// rows [HW,2HW): fused = (Aw@Wo)/(wsum+1e-6) + bo*wsum/(wsum+1e-6)
__global__ void __launch_bounds__(256) outproj_kernel(
    const float* __restrict__ Wo, const float* __restrict__ bo,
    float* __restrict__ out)
{
    float acc[4][4];
    gemm_tile(g_A, Wo, 2 * HW, CMODEL, acc, CMODEL);
    int row0 = blockIdx.y * 64, col0 = blockIdx.x * 64;
    int tx = threadIdx.x, ty = threadIdx.y;
    int c0 = col0 + tx * 4;
    float b0 = bo[c0 + 0], b1 = bo[c0 + 1], b2 = bo[c0 + 2], b3 = bo[c0 + 3];
    #pragma unroll
    for (int i = 0; i < 4; ++i) {
        int r = row0 + ty * 4 + i;
        float4 o;
        if (r < HW) {
            o = make_float4(acc[i][0] + b0, acc[i][1] + b1,
                            acc[i][2] + b2, acc[i][3] + b3);
        } else {
            int pp = r - HW;
            float ws = g_wsum[pp];
            float invD = 1.f / (ws + 1e-6f);
            float bs = ws * invD;
            o = make_float4(acc[i][0] * invD + b0 * bs,
                            acc[i][1] * invD + b1 * bs,
                            acc[i][2] * invD + b2 * bs,
                            acc[i][3] * invD + b3 * bs);
        }
        *(float4*)(out + (size_t)r * CMODEL + c0) = o;
    }
}

// ---------------- launch ---------------------------------------------------
extern "C" void kernel_launch(void* const* d_in, const int* in_sizes, int n_in,
                              void* d_out, int out_size)
{
    (void)in_sizes; (void)n_in; (void)out_size;
    const float* hs  = (const float*)d_in[0];   // (2, 4096, 320)
    const float* ehs = (const float*)d_in[1];   // (11, 77, 768); use first 10
    const float* bb  = (const float*)d_in[2];   // (1, 8, 4)
    const float* Wq  = (const float*)d_in[3];
    const float* Wk  = (const float*)d_in[4];
    const float* Wv  = (const float*)d_in[5];
    const float* Wo  = (const float*)d_in[6];
    const float* bo  = (const float*)d_in[7];
    float* out = (float*)d_out;

    weights_kernel<<<16, 256>>>(bb);

    dim3 blk(16, 16);
    qproj_kernel<<<dim3(CMODEL / 64, (2 * HW) / 64), blk>>>(hs, Wq);
    kproj_kernel<<<dim3(CMODEL / 64, (NB * LSEQ + 63) / 64), blk>>>(ehs, Wk);
    vproj_kernel<<<dim3(CMODEL / 64, (NB * LSEQ + 63) / 64), blk>>>(ehs, Wv);

    att_kernel<<<dim3(HW / AT_ROWS, HEADS), AT_ROWS>>>();

    outproj_kernel<<<dim3(CMODEL / 64, (2 * HW) / 64), blk>>>(Wo, bo, out);
}

// round 8
// speedup vs baseline: 1.0820x; 1.0820x over previous
#include <cuda_runtime.h>
#include <math.h>

#define HEADS 8
#define DHEAD 40
#define D4 10            // DHEAD/4
#define CMODEL 320
#define CX 768
#define LSEQ 77
#define NB 10
#define HW 4096
#define NPHASE 9
#define AT_ROWS 64

// ---------------- scratch (device globals; no allocation allowed) ----------
__device__ __align__(16) float g_q[2 * HW * CMODEL];
__device__ __align__(16) float g_k[NB * LSEQ * CMODEL];
__device__ __align__(16) float g_v[NB * LSEQ * CMODEL];
__device__ __align__(16) float g_A[2 * HW * CMODEL];   // [0:HW)=uncond, [HW:2HW)=weighted sum
__device__ __align__(16) float g_w9[NPHASE * HW];
__device__ __align__(16) float g_wsum[HW];

// ---------------- phase weights (jax.image.resize bilinear+antialias) ------
__device__ __forceinline__ float resize_factor(int o, float lo, float hi) {
    float sf = (o + 0.5f) * 8.0f - 0.5f;
    float num = 0.f, den = 0.f;
    int h0 = o * 8 - 4, h1 = o * 8 + 11;
    #pragma unroll 1
    for (int h = h0; h <= h1; ++h) {
        if (h < 0 || h > 511) continue;
        float fh = (float)h;
        float wgt = 1.0f - fabsf(fh - sf) * 0.125f;
        den += wgt;
        if (fh >= lo && fh < hi) num += wgt;
    }
    return num / den;
}

__global__ void weights_kernel(const float* __restrict__ bboxes) {
    int p = blockIdx.x * blockDim.x + threadIdx.x;
    if (p >= HW) return;
    int r = p >> 6, c = p & 63;
    float s = 0.1f;
    g_w9[p] = 0.1f;
    #pragma unroll 1
    for (int i = 0; i < 8; ++i) {
        float x0 = bboxes[i * 4 + 0], y0 = bboxes[i * 4 + 1];
        float x1 = bboxes[i * 4 + 2], y1 = bboxes[i * 4 + 3];
        float wmin = floorf(512.f * x0), wmax = floorf(512.f * x1);
        float hmin = floorf(512.f * y0), hmax = floorf(512.f * y1);
        float wv = 10.f * resize_factor(r, hmin, hmax) * resize_factor(c, wmin, wmax);
        g_w9[(i + 1) * HW + p] = wv;
        s += wv;
    }
    g_wsum[p] = s;
}

// ---------------- fused K+V projection: [770,768] x {Wk,Wv} ----------------
// 64x64 tile, BK=16, 256 threads, 4x4 micro per output matrix (32 FMA / 3 LDS.128)
__global__ void __launch_bounds__(256) kvproj_kernel(
    const float* __restrict__ ehs,
    const float* __restrict__ Wk, const float* __restrict__ Wv)
{
    __shared__ __align__(16) float As[16][72];
    __shared__ __align__(16) float Bk[16][64];
    __shared__ __align__(16) float Bv[16][64];
    const int tx = threadIdx.x, ty = threadIdx.y;
    const int t  = ty * 16 + tx;
    const int row0 = blockIdx.y * 64, col0 = blockIdx.x * 64;
    const int li = t >> 2, lk = (t & 3) << 2;
    const int bk = t >> 4, bj = (t & 15) << 2;

    float ak[4][4], av[4][4];
    #pragma unroll
    for (int i = 0; i < 4; ++i)
        #pragma unroll
        for (int j = 0; j < 4; ++j) { ak[i][j] = 0.f; av[i][j] = 0.f; }

    for (int k0 = 0; k0 < CX; k0 += 16) {
        // rows up to 831 are still inside ehs (847 rows) — unguarded load is safe
        float4 a = *(const float4*)(ehs + (size_t)(row0 + li) * CX + k0 + lk);
        As[lk + 0][li] = a.x; As[lk + 1][li] = a.y;
        As[lk + 2][li] = a.z; As[lk + 3][li] = a.w;
        *(float4*)(&Bk[bk][bj]) = *(const float4*)(Wk + (size_t)(k0 + bk) * CMODEL + col0 + bj);
        *(float4*)(&Bv[bk][bj]) = *(const float4*)(Wv + (size_t)(k0 + bk) * CMODEL + col0 + bj);
        __syncthreads();
        #pragma unroll
        for (int kk = 0; kk < 16; ++kk) {
            float4 av4 = *(const float4*)(&As[kk][ty * 4]);
            float4 b1  = *(const float4*)(&Bk[kk][tx * 4]);
            float4 b2  = *(const float4*)(&Bv[kk][tx * 4]);
            ak[0][0] += av4.x * b1.x; ak[0][1] += av4.x * b1.y; ak[0][2] += av4.x * b1.z; ak[0][3] += av4.x * b1.w;
            ak[1][0] += av4.y * b1.x; ak[1][1] += av4.y * b1.y; ak[1][2] += av4.y * b1.z; ak[1][3] += av4.y * b1.w;
            ak[2][0] += av4.z * b1.x; ak[2][1] += av4.z * b1.y; ak[2][2] += av4.z * b1.z; ak[2][3] += av4.z * b1.w;
            ak[3][0] += av4.w * b1.x; ak[3][1] += av4.w * b1.y; ak[3][2] += av4.w * b1.z; ak[3][3] += av4.w * b1.w;
            av[0][0] += av4.x * b2.x; av[0][1] += av4.x * b2.y; av[0][2] += av4.x * b2.z; av[0][3] += av4.x * b2.w;
            av[1][0] += av4.y * b2.x; av[1][1] += av4.y * b2.y; av[1][2] += av4.y * b2.z; av[1][3] += av4.y * b2.w;
            av[2][0] += av4.z * b2.x; av[2][1] += av4.z * b2.y; av[2][2] += av4.z * b2.z; av[2][3] += av4.z * b2.w;
            av[3][0] += av4.w * b2.x; av[3][1] += av4.w * b2.y; av[3][2] += av4.w * b2.z; av[3][3] += av4.w * b2.w;
        }
        __syncthreads();
    }
    #pragma unroll
    for (int i = 0; i < 4; ++i) {
        int r = row0 + ty * 4 + i;
        if (r >= NB * LSEQ) continue;
        *(float4*)(g_k + (size_t)r * CMODEL + col0 + tx * 4) =
            make_float4(ak[i][0], ak[i][1], ak[i][2], ak[i][3]);
        *(float4*)(g_v + (size_t)r * CMODEL + col0 + tx * 4) =
            make_float4(av[i][0], av[i][1], av[i][2], av[i][3]);
    }
}

// ---------------- 128x64 tile GEMM core, BK=16, 256 threads, 8x4 micro -----
__device__ __forceinline__ void gemm128_tile(
    const float* __restrict__ A, const float* __restrict__ B,
    int K, int N, float (&acc)[8][4])
{
    __shared__ __align__(16) float As[16][132];   // 132*4=528B row stride, 16B-aligned
    __shared__ __align__(16) float Bs[16][64];
    const int tx = threadIdx.x, ty = threadIdx.y;
    const int t  = ty * 16 + tx;
    const int row0 = blockIdx.y * 128, col0 = blockIdx.x * 64;
    const int li = t >> 1, lk = (t & 1) << 3;     // 8 floats of A per thread
    const int bk = t >> 4, bj = (t & 15) << 2;

    #pragma unroll
    for (int i = 0; i < 8; ++i)
        #pragma unroll
        for (int j = 0; j < 4; ++j) acc[i][j] = 0.f;

    for (int k0 = 0; k0 < K; k0 += 16) {
        const float* ap = A + (size_t)(row0 + li) * K + k0 + lk;
        float4 a0 = *(const float4*)(ap);
        float4 a1 = *(const float4*)(ap + 4);
        As[lk + 0][li] = a0.x; As[lk + 1][li] = a0.y;
        As[lk + 2][li] = a0.z; As[lk + 3][li] = a0.w;
        As[lk + 4][li] = a1.x; As[lk + 5][li] = a1.y;
        As[lk + 6][li] = a1.z; As[lk + 7][li] = a1.w;
        *(float4*)(&Bs[bk][bj]) = *(const float4*)(B + (size_t)(k0 + bk) * N + col0 + bj);
        __syncthreads();
        #pragma unroll
        for (int kk = 0; kk < 16; ++kk) {
            float4 alo = *(const float4*)(&As[kk][ty * 8]);
            float4 ahi = *(const float4*)(&As[kk][ty * 8 + 4]);
            float4 b   = *(const float4*)(&Bs[kk][tx * 4]);
            acc[0][0] += alo.x * b.x; acc[0][1] += alo.x * b.y; acc[0][2] += alo.x * b.z; acc[0][3] += alo.x * b.w;
            acc[1][0] += alo.y * b.x; acc[1][1] += alo.y * b.y; acc[1][2] += alo.y * b.z; acc[1][3] += alo.y * b.w;
            acc[2][0] += alo.z * b.x; acc[2][1] += alo.z * b.y; acc[2][2] += alo.z * b.z; acc[2][3] += alo.z * b.w;
            acc[3][0] += alo.w * b.x; acc[3][1] += alo.w * b.y; acc[3][2] += alo.w * b.z; acc[3][3] += alo.w * b.w;
            acc[4][0] += ahi.x * b.x; acc[4][1] += ahi.x * b.y; acc[4][2] += ahi.x * b.z; acc[4][3] += ahi.x * b.w;
            acc[5][0] += ahi.y * b.x; acc[5][1] += ahi.y * b.y; acc[5][2] += ahi.y * b.z; acc[5][3] += ahi.y * b.w;
            acc[6][0] += ahi.z * b.x; acc[6][1] += ahi.z * b.y; acc[6][2] += ahi.z * b.z; acc[6][3] += ahi.z * b.w;
            acc[7][0] += ahi.w * b.x; acc[7][1] += ahi.w * b.y; acc[7][2] += ahi.w * b.z; acc[7][3] += ahi.w * b.w;
        }
        __syncthreads();
    }
}

// Q projection: [8192,320] x [320,320] -> g_q  (M divisible by 128, no guards)
__global__ void __launch_bounds__(256) qproj_kernel(
    const float* __restrict__ hs, const float* __restrict__ Wq)
{
    float acc[8][4];
    gemm128_tile(hs, Wq, CMODEL, CMODEL, acc);
    const int row0 = blockIdx.y * 128, col0 = blockIdx.x * 64;
    const int tx = threadIdx.x, ty = threadIdx.y;
    #pragma unroll
    for (int i = 0; i < 8; ++i) {
        int r = row0 + ty * 8 + i;
        *(float4*)(g_q + (size_t)r * CMODEL + col0 + tx * 4) =
            make_float4(acc[i][0], acc[i][1], acc[i][2], acc[i][3]);
    }
}

// Output projection + fused epilogue
__global__ void __launch_bounds__(256) outproj_kernel(
    const float* __restrict__ Wo, const float* __restrict__ bo,
    float* __restrict__ out)
{
    float acc[8][4];
    gemm128_tile(g_A, Wo, CMODEL, CMODEL, acc);
    const int row0 = blockIdx.y * 128, col0 = blockIdx.x * 64;
    const int tx = threadIdx.x, ty = threadIdx.y;
    const int c0 = col0 + tx * 4;
    float b0 = bo[c0 + 0], b1 = bo[c0 + 1], b2 = bo[c0 + 2], b3 = bo[c0 + 3];
    #pragma unroll
    for (int i = 0; i < 8; ++i) {
        int r = row0 + ty * 8 + i;
        float4 o;
        if (r < HW) {
            o = make_float4(acc[i][0] + b0, acc[i][1] + b1,
                            acc[i][2] + b2, acc[i][3] + b3);
        } else {
            float ws = g_wsum[r - HW];
            float invD = 1.f / (ws + 1e-6f);
            float bs = ws * invD;
            o = make_float4(acc[i][0] * invD + b0 * bs,
                            acc[i][1] * invD + b1 * bs,
                            acc[i][2] * invD + b2 * bs,
                            acc[i][3] * invD + b3 * bs);
        }
        *(float4*)(out + (size_t)r * CMODEL + c0) = o;
    }
}

// ---------------- attention: 10 batches fused, float4 inner loops ----------
__global__ void __launch_bounds__(64) att_kernel()
{
    __shared__ __align__(16) float4 ks4[LSEQ * D4];
    __shared__ __align__(16) float4 vs4[LSEQ * D4];
    __shared__ float sc[AT_ROWS * LSEQ];   // stride 77 -> conflict-free
    const int head = blockIdx.y;
    const int t = threadIdx.x;
    const int p = blockIdx.x * AT_ROWS + t;
    float* mysc = sc + t * LSEQ;
    const float scale = 0.15811388300841897f;   // 1/sqrt(40)

    float4 q4[D4];
    float4 aw[D4];
    #pragma unroll
    for (int d = 0; d < D4; ++d) aw[d] = make_float4(0.f, 0.f, 0.f, 0.f);

    for (int b = 0; b < NB; ++b) {
        // stage K/V head tile (77 x 40) as float4s
        const float4* gk4 = (const float4*)g_k;
        const float4* gv4 = (const float4*)g_v;
        for (int idx = t; idx < LSEQ * D4; idx += AT_ROWS) {
            int j = idx / D4, d = idx - j * D4;
            int g = (b * LSEQ + j) * (CMODEL / 4) + head * D4 + d;
            ks4[idx] = gk4[g];
            vs4[idx] = gv4[g];
        }
        __syncthreads();

        if (b < 2) {
            const float4* qp = (const float4*)(g_q + ((size_t)b * HW + p) * CMODEL + head * DHEAD);
            #pragma unroll
            for (int d = 0; d < D4; ++d) q4[d] = qp[d];
        }

        // pass 1: scores + rowmax
        float m = -1e30f;
        #pragma unroll 1
        for (int j = 0; j < LSEQ; ++j) {
            const float4* kj = ks4 + j * D4;
            float s0 = 0.f, s1 = 0.f, s2 = 0.f, s3 = 0.f;
            #pragma unroll
            for (int d = 0; d < D4; ++d) {
                float4 k = kj[d];
                s0 += q4[d].x * k.x; s1 += q4[d].y * k.y;
                s2 += q4[d].z * k.z; s3 += q4[d].w * k.w;
            }
            float s = ((s0 + s1) + (s2 + s3)) * scale;
            mysc[j] = s;
            m = fmaxf(m, s);
        }

        // pass 2: softmax + PV
        float4 acc[D4];
        #pragma unroll
        for (int d = 0; d < D4; ++d) acc[d] = make_float4(0.f, 0.f, 0.f, 0.f);
        float l = 0.f;
        #pragma unroll 1
        for (int j = 0; j < LSEQ; ++j) {
            float pe = __expf(mysc[j] - m);
            l += pe;
            const float4* vj = vs4 + j * D4;
            #pragma unroll
            for (int d = 0; d < D4; ++d) {
                float4 v = vj[d];
                acc[d].x += pe * v.x; acc[d].y += pe * v.y;
                acc[d].z += pe * v.z; acc[d].w += pe * v.w;
            }
        }
        float inv = 1.f / l;

        if (b == 0) {
            float4* o = (float4*)(g_A + (size_t)p * CMODEL + head * DHEAD);
            #pragma unroll
            for (int d = 0; d < D4; ++d)
                o[d] = make_float4(acc[d].x * inv, acc[d].y * inv,
                                   acc[d].z * inv, acc[d].w * inv);
        } else {
            float wg = g_w9[(b - 1) * HW + p] * inv;
            #pragma unroll
            for (int d = 0; d < D4; ++d) {
                aw[d].x += wg * acc[d].x; aw[d].y += wg * acc[d].y;
                aw[d].z += wg * acc[d].z; aw[d].w += wg * acc[d].w;
            }
        }
        __syncthreads();
    }
    float4* o = (float4*)(g_A + (size_t)(HW + p) * CMODEL + head * DHEAD);
    #pragma unroll
    for (int d = 0; d < D4; ++d) o[d] = aw[d];
}

// ---------------- launch ---------------------------------------------------
extern "C" void kernel_launch(void* const* d_in, const int* in_sizes, int n_in,
                              void* d_out, int out_size)
{
    (void)in_sizes; (void)n_in; (void)out_size;
    const float* hs  = (const float*)d_in[0];
    const float* ehs = (const float*)d_in[1];
    const float* bb  = (const float*)d_in[2];
    const float* Wq  = (const float*)d_in[3];
    const float* Wk  = (const float*)d_in[4];
    const float* Wv  = (const float*)d_in[5];
    const float* Wo  = (const float*)d_in[6];
    const float* bo  = (const float*)d_in[7];
    float* out = (float*)d_out;

    weights_kernel<<<16, 256>>>(bb);

    dim3 blk(16, 16);
    qproj_kernel<<<dim3(CMODEL / 64, (2 * HW) / 128), blk>>>(hs, Wq);
    kvproj_kernel<<<dim3(CMODEL / 64, (NB * LSEQ + 63) / 64), blk>>>(ehs, Wk, Wv);

    att_kernel<<<dim3(HW / AT_ROWS, HEADS), AT_ROWS>>>();

    outproj_kernel<<<dim3(CMODEL / 64, (2 * HW) / 128), blk>>>(Wo, bo, out);
}

// round 9
// speedup vs baseline: 1.2225x; 1.1298x over previous
#include <cuda_runtime.h>
#include <math.h>

#define HEADS 8
#define DHEAD 40
#define CMODEL 320
#define CX 768
#define LSEQ 77
#define NB 10
#define HW 4096
#define NPHASE 9

typedef unsigned long long u64;

// ---------------- packed f32x2 helpers (FFMA2 path, sm_100+) ---------------
__device__ __forceinline__ u64 pack2(float lo, float hi) {
    u64 r; asm("mov.b64 %0, {%1, %2};" : "=l"(r) : "f"(lo), "f"(hi)); return r;
}
__device__ __forceinline__ float2 unpk2(u64 v) {
    float2 f; asm("mov.b64 {%0, %1}, %2;" : "=f"(f.x), "=f"(f.y) : "l"(v)); return f;
}
__device__ __forceinline__ u64 ffma2(u64 a, u64 b, u64 c) {
    u64 d; asm("fma.rn.f32x2 %0, %1, %2, %3;" : "=l"(d) : "l"(a), "l"(b), "l"(c)); return d;
}

// ---------------- scratch (device globals; no allocation allowed) ----------
__device__ __align__(16) float g_q[2 * HW * CMODEL];
__device__ __align__(16) float g_k[NB * LSEQ * CMODEL];
__device__ __align__(16) float g_v[NB * LSEQ * CMODEL];
__device__ __align__(16) float g_A[2 * HW * CMODEL];     // [0:HW)=uncond, [HW:2HW)=weighted sum
__device__ __align__(16) float g_O[NPHASE * HW * CMODEL]; // per-batch weighted outputs (b=1..9)
__device__ __align__(16) float g_w9[NPHASE * HW];
__device__ __align__(16) float g_wsum[HW];

// ---------------- phase weights (jax.image.resize bilinear+antialias) ------
__device__ __forceinline__ float resize_factor(int o, float lo, float hi) {
    float sf = (o + 0.5f) * 8.0f - 0.5f;
    float num = 0.f, den = 0.f;
    int h0 = o * 8 - 4, h1 = o * 8 + 11;
    #pragma unroll 1
    for (int h = h0; h <= h1; ++h) {
        if (h < 0 || h > 511) continue;
        float fh = (float)h;
        float wgt = 1.0f - fabsf(fh - sf) * 0.125f;
        den += wgt;
        if (fh >= lo && fh < hi) num += wgt;
    }
    return num / den;
}

__global__ void weights_kernel(const float* __restrict__ bboxes) {
    int p = blockIdx.x * blockDim.x + threadIdx.x;
    if (p >= HW) return;
    int r = p >> 6, c = p & 63;
    float s = 0.1f;
    g_w9[p] = 0.1f;
    #pragma unroll 1
    for (int i = 0; i < 8; ++i) {
        float x0 = bboxes[i * 4 + 0], y0 = bboxes[i * 4 + 1];
        float x1 = bboxes[i * 4 + 2], y1 = bboxes[i * 4 + 3];
        float wmin = floorf(512.f * x0), wmax = floorf(512.f * x1);
        float hmin = floorf(512.f * y0), hmax = floorf(512.f * y1);
        float wv = 10.f * resize_factor(r, hmin, hmax) * resize_factor(c, wmin, wmax);
        g_w9[(i + 1) * HW + p] = wv;
        s += wv;
    }
    g_wsum[p] = s;
}

// ---------------- fused K+V projection: 64x64 tile, FFMA2 row-pairs --------
__global__ void __launch_bounds__(256) kvproj_kernel(
    const float* __restrict__ ehs,
    const float* __restrict__ Wk, const float* __restrict__ Wv)
{
    __shared__ __align__(16) float As[16][72];
    __shared__ __align__(16) float Bk[16][64];
    __shared__ __align__(16) float Bv[16][64];
    const int tx = threadIdx.x, ty = threadIdx.y;
    const int t  = ty * 16 + tx;
    const int row0 = blockIdx.y * 64, col0 = blockIdx.x * 64;
    const int li = t >> 2, lk = (t & 3) << 2;
    const int bk = t >> 4, bj = (t & 15) << 2;

    u64 ak[2][4], av[2][4];
    #pragma unroll
    for (int i = 0; i < 2; ++i)
        #pragma unroll
        for (int j = 0; j < 4; ++j) { ak[i][j] = 0ULL; av[i][j] = 0ULL; }

    for (int k0 = 0; k0 < CX; k0 += 16) {
        // rows up to 831 < 847 total in ehs — unguarded load is safe
        float4 a = *(const float4*)(ehs + (size_t)(row0 + li) * CX + k0 + lk);
        As[lk + 0][li] = a.x; As[lk + 1][li] = a.y;
        As[lk + 2][li] = a.z; As[lk + 3][li] = a.w;
        *(float4*)(&Bk[bk][bj]) = *(const float4*)(Wk + (size_t)(k0 + bk) * CMODEL + col0 + bj);
        *(float4*)(&Bv[bk][bj]) = *(const float4*)(Wv + (size_t)(k0 + bk) * CMODEL + col0 + bj);
        __syncthreads();
        #pragma unroll
        for (int kk = 0; kk < 16; ++kk) {
            ulonglong2 ap = *(const ulonglong2*)(&As[kk][ty * 4]);  // row pairs (0,1),(2,3)
            float4 b1 = *(const float4*)(&Bk[kk][tx * 4]);
            float4 b2 = *(const float4*)(&Bv[kk][tx * 4]);
            u64 k0s = pack2(b1.x, b1.x), k1s = pack2(b1.y, b1.y);
            u64 k2s = pack2(b1.z, b1.z), k3s = pack2(b1.w, b1.w);
            u64 v0s = pack2(b2.x, b2.x), v1s = pack2(b2.y, b2.y);
            u64 v2s = pack2(b2.z, b2.z), v3s = pack2(b2.w, b2.w);
            ak[0][0] = ffma2(ap.x, k0s, ak[0][0]); ak[0][1] = ffma2(ap.x, k1s, ak[0][1]);
            ak[0][2] = ffma2(ap.x, k2s, ak[0][2]); ak[0][3] = ffma2(ap.x, k3s, ak[0][3]);
            ak[1][0] = ffma2(ap.y, k0s, ak[1][0]); ak[1][1] = ffma2(ap.y, k1s, ak[1][1]);
            ak[1][2] = ffma2(ap.y, k2s, ak[1][2]); ak[1][3] = ffma2(ap.y, k3s, ak[1][3]);
            av[0][0] = ffma2(ap.x, v0s, av[0][0]); av[0][1] = ffma2(ap.x, v1s, av[0][1]);
            av[0][2] = ffma2(ap.x, v2s, av[0][2]); av[0][3] = ffma2(ap.x, v3s, av[0][3]);
            av[1][0] = ffma2(ap.y, v0s, av[1][0]); av[1][1] = ffma2(ap.y, v1s, av[1][1]);
            av[1][2] = ffma2(ap.y, v2s, av[1][2]); av[1][3] = ffma2(ap.y, v3s, av[1][3]);
        }
        __syncthreads();
    }
    #pragma unroll
    for (int i = 0; i < 2; ++i) {
        float2 c0 = unpk2(ak[i][0]), c1 = unpk2(ak[i][1]);
        float2 c2 = unpk2(ak[i][2]), c3 = unpk2(ak[i][3]);
        float2 d0 = unpk2(av[i][0]), d1 = unpk2(av[i][1]);
        float2 d2 = unpk2(av[i][2]), d3 = unpk2(av[i][3]);
        int re = row0 + ty * 4 + 2 * i;
        if (re < NB * LSEQ) {
            *(float4*)(g_k + (size_t)re * CMODEL + col0 + tx * 4) = make_float4(c0.x, c1.x, c2.x, c3.x);
            *(float4*)(g_v + (size_t)re * CMODEL + col0 + tx * 4) = make_float4(d0.x, d1.x, d2.x, d3.x);
        }
        if (re + 1 < NB * LSEQ) {
            *(float4*)(g_k + (size_t)(re + 1) * CMODEL + col0 + tx * 4) = make_float4(c0.y, c1.y, c2.y, c3.y);
            *(float4*)(g_v + (size_t)(re + 1) * CMODEL + col0 + tx * 4) = make_float4(d0.y, d1.y, d2.y, d3.y);
        }
    }
}

// ---------------- 128x64 tile GEMM core, FFMA2 row-pair micro --------------
__device__ __forceinline__ void gemm128_f2(
    const float* __restrict__ A, const float* __restrict__ B,
    int K, int N, u64 (&acc)[4][4])
{
    __shared__ __align__(16) float As[16][132];
    __shared__ __align__(16) float Bs[16][64];
    const int tx = threadIdx.x, ty = threadIdx.y;
    const int t  = ty * 16 + tx;
    const int row0 = blockIdx.y * 128, col0 = blockIdx.x * 64;
    const int li = t >> 1, lk = (t & 1) << 3;
    const int bk = t >> 4, bj = (t & 15) << 2;

    #pragma unroll
    for (int i = 0; i < 4; ++i)
        #pragma unroll
        for (int j = 0; j < 4; ++j) acc[i][j] = 0ULL;

    for (int k0 = 0; k0 < K; k0 += 16) {
        const float* ap = A + (size_t)(row0 + li) * K + k0 + lk;
        float4 a0 = *(const float4*)(ap);
        float4 a1 = *(const float4*)(ap + 4);
        As[lk + 0][li] = a0.x; As[lk + 1][li] = a0.y;
        As[lk + 2][li] = a0.z; As[lk + 3][li] = a0.w;
        As[lk + 4][li] = a1.x; As[lk + 5][li] = a1.y;
        As[lk + 6][li] = a1.z; As[lk + 7][li] = a1.w;
        *(float4*)(&Bs[bk][bj]) = *(const float4*)(B + (size_t)(k0 + bk) * N + col0 + bj);
        __syncthreads();
        #pragma unroll
        for (int kk = 0; kk < 16; ++kk) {
            const ulonglong2* ar = (const ulonglong2*)(&As[kk][ty * 8]);
            ulonglong2 alo = ar[0], ahi = ar[1];   // row pairs (0,1),(2,3),(4,5),(6,7)
            float4 b = *(const float4*)(&Bs[kk][tx * 4]);
            u64 b0 = pack2(b.x, b.x), b1 = pack2(b.y, b.y);
            u64 b2 = pack2(b.z, b.z), b3 = pack2(b.w, b.w);
            acc[0][0] = ffma2(alo.x, b0, acc[0][0]); acc[0][1] = ffma2(alo.x, b1, acc[0][1]);
            acc[0][2] = ffma2(alo.x, b2, acc[0][2]); acc[0][3] = ffma2(alo.x, b3, acc[0][3]);
            acc[1][0] = ffma2(alo.y, b0, acc[1][0]); acc[1][1] = ffma2(alo.y, b1, acc[1][1]);
            acc[1][2] = ffma2(alo.y, b2, acc[1][2]); acc[1][3] = ffma2(alo.y, b3, acc[1][3]);
            acc[2][0] = ffma2(ahi.x, b0, acc[2][0]); acc[2][1] = ffma2(ahi.x, b1, acc[2][1]);
            acc[2][2] = ffma2(ahi.x, b2, acc[2][2]); acc[2][3] = ffma2(ahi.x, b3, acc[2][3]);
            acc[3][0] = ffma2(ahi.y, b0, acc[3][0]); acc[3][1] = ffma2(ahi.y, b1, acc[3][1]);
            acc[3][2] = ffma2(ahi.y, b2, acc[3][2]); acc[3][3] = ffma2(ahi.y, b3, acc[3][3]);
        }
        __syncthreads();
    }
}

// Q projection: [8192,320] x [320,320] -> g_q
__global__ void __launch_bounds__(256) qproj_kernel(
    const float* __restrict__ hs, const float* __restrict__ Wq)
{
    u64 acc[4][4];
    gemm128_f2(hs, Wq, CMODEL, CMODEL, acc);
    const int row0 = blockIdx.y * 128, col0 = blockIdx.x * 64;
    const int tx = threadIdx.x, ty = threadIdx.y;
    #pragma unroll
    for (int i = 0; i < 4; ++i) {
        float2 c0 = unpk2(acc[i][0]), c1 = unpk2(acc[i][1]);
        float2 c2 = unpk2(acc[i][2]), c3 = unpk2(acc[i][3]);
        int re = row0 + ty * 8 + 2 * i;
        *(float4*)(g_q + (size_t)re * CMODEL + col0 + tx * 4) = make_float4(c0.x, c1.x, c2.x, c3.x);
        *(float4*)(g_q + (size_t)(re + 1) * CMODEL + col0 + tx * 4) = make_float4(c0.y, c1.y, c2.y, c3.y);
    }
}

// Output projection + fused epilogue
__global__ void __launch_bounds__(256) outproj_kernel(
    const float* __restrict__ Wo, const float* __restrict__ bo,
    float* __restrict__ out)
{
    u64 acc[4][4];
    gemm128_f2(g_A, Wo, CMODEL, CMODEL, acc);
    const int row0 = blockIdx.y * 128, col0 = blockIdx.x * 64;
    const int tx = threadIdx.x, ty = threadIdx.y;
    const int c0i = col0 + tx * 4;
    float b0 = bo[c0i + 0], b1 = bo[c0i + 1], b2 = bo[c0i + 2], b3 = bo[c0i + 3];
    #pragma unroll
    for (int i = 0; i < 4; ++i) {
        float2 c0 = unpk2(acc[i][0]), c1 = unpk2(acc[i][1]);
        float2 c2 = unpk2(acc[i][2]), c3 = unpk2(acc[i][3]);
        float vals[2][4] = {{c0.x, c1.x, c2.x, c3.x}, {c0.y, c1.y, c2.y, c3.y}};
        #pragma unroll
        for (int h = 0; h < 2; ++h) {
            int r = row0 + ty * 8 + 2 * i + h;
            float4 o;
            if (r < HW) {
                o = make_float4(vals[h][0] + b0, vals[h][1] + b1,
                                vals[h][2] + b2, vals[h][3] + b3);
            } else {
                float ws = g_wsum[r - HW];
                float invD = 1.f / (ws + 1e-6f);
                float bs = ws * invD;
                o = make_float4(vals[h][0] * invD + b0 * bs,
                                vals[h][1] * invD + b1 * bs,
                                vals[h][2] * invD + b2 * bs,
                                vals[h][3] * invD + b3 * bs);
            }
            *(float4*)(out + (size_t)r * CMODEL + c0i) = o;
        }
    }
}

// ---------------- attention: one (q-tile, head, batch) per block -----------
// Single-pass softmax (no max subtraction: |scores| <~ 1.5, safe in fp32).
// b==0 -> g_A[0:HW); b>=1 -> weighted output into g_O[b-1].
__global__ void __launch_bounds__(128) att_kernel()
{
    __shared__ __align__(16) u64 ks[LSEQ * 20];   // 77 rows x 40 floats (20 u64)
    __shared__ __align__(16) u64 vs[LSEQ * 20];
    const int head = blockIdx.y;
    const int b = blockIdx.z;
    const int t = threadIdx.x;
    const int p = blockIdx.x * 128 + t;
    const float scale = 0.15811388300841897f;     // 1/sqrt(40)

    // stage K/V head tile (16B vectors; CMODEL row = 80 ulonglong2)
    {
        const ulonglong2* gk = (const ulonglong2*)g_k;
        const ulonglong2* gv = (const ulonglong2*)g_v;
        ulonglong2* ks2 = (ulonglong2*)ks;
        ulonglong2* vs2 = (ulonglong2*)vs;
        for (int idx = t; idx < LSEQ * 10; idx += 128) {
            int j = idx / 10, d = idx - j * 10;
            int g = (b * LSEQ + j) * 80 + head * 10 + d;
            ks2[idx] = gk[g];
            vs2[idx] = gv[g];
        }
    }
    __syncthreads();

    // load q row (packed pairs)
    u64 q2[20];
    {
        int qb = (b == 0) ? 0 : 1;
        const ulonglong2* qp = (const ulonglong2*)(g_q + ((size_t)qb * HW + p) * CMODEL + head * DHEAD);
        #pragma unroll
        for (int d = 0; d < 10; ++d) {
            ulonglong2 qq = qp[d];
            q2[2 * d] = qq.x; q2[2 * d + 1] = qq.y;
        }
    }

    u64 acc2[20];
    #pragma unroll
    for (int d = 0; d < 20; ++d) acc2[d] = 0ULL;
    float l = 0.f;

    #pragma unroll 1
    for (int j = 0; j < LSEQ; ++j) {
        const ulonglong2* kj = (const ulonglong2*)(ks + j * 20);
        u64 sA = 0ULL, sB = 0ULL;
        #pragma unroll
        for (int d = 0; d < 10; ++d) {
            ulonglong2 kk = kj[d];
            sA = ffma2(q2[2 * d], kk.x, sA);
            sB = ffma2(q2[2 * d + 1], kk.y, sB);
        }
        float2 fa = unpk2(sA), fb = unpk2(sB);
        float s = ((fa.x + fa.y) + (fb.x + fb.y)) * scale;
        float pe = __expf(s);
        l += pe;
        u64 pe2 = pack2(pe, pe);
        const ulonglong2* vj = (const ulonglong2*)(vs + j * 20);
        #pragma unroll
        for (int d = 0; d < 10; ++d) {
            ulonglong2 vv = vj[d];
            acc2[2 * d]     = ffma2(pe2, vv.x, acc2[2 * d]);
            acc2[2 * d + 1] = ffma2(pe2, vv.y, acc2[2 * d + 1]);
        }
    }

    float inv = 1.f / l;
    float sc;
    float* optr;
    if (b == 0) {
        sc = inv;
        optr = g_A + (size_t)p * CMODEL + head * DHEAD;
    } else {
        sc = g_w9[(b - 1) * HW + p] * inv;   // pre-weighted; reduce kernel just sums
        optr = g_O + ((size_t)(b - 1) * HW + p) * CMODEL + head * DHEAD;
    }
    float4* o4 = (float4*)optr;
    #pragma unroll
    for (int d = 0; d < 10; ++d) {
        float2 x = unpk2(acc2[2 * d]);
        float2 y = unpk2(acc2[2 * d + 1]);
        o4[d] = make_float4(x.x * sc, x.y * sc, y.x * sc, y.y * sc);
    }
}

// ---------------- sum the 9 pre-weighted batch outputs ---------------------
__global__ void __launch_bounds__(256) reduce9_kernel()
{
    int idx = blockIdx.x * 256 + threadIdx.x;   // over HW*CMODEL/4 float4s
    const float4* o4 = (const float4*)g_O;
    const size_t stride = (size_t)HW * CMODEL / 4;
    float4 s = o4[idx];
    #pragma unroll
    for (int bb = 1; bb < NPHASE; ++bb) {
        float4 v = o4[bb * stride + idx];
        s.x += v.x; s.y += v.y; s.z += v.z; s.w += v.w;
    }
    ((float4*)(g_A + (size_t)HW * CMODEL))[idx] = s;
}

// ---------------- launch ---------------------------------------------------
extern "C" void kernel_launch(void* const* d_in, const int* in_sizes, int n_in,
                              void* d_out, int out_size)
{
    (void)in_sizes; (void)n_in; (void)out_size;
    const float* hs  = (const float*)d_in[0];
    const float* ehs = (const float*)d_in[1];
    const float* bb  = (const float*)d_in[2];
    const float* Wq  = (const float*)d_in[3];
    const float* Wk  = (const float*)d_in[4];
    const float* Wv  = (const float*)d_in[5];
    const float* Wo  = (const float*)d_in[6];
    const float* bo  = (const float*)d_in[7];
    float* out = (float*)d_out;

    weights_kernel<<<16, 256>>>(bb);

    dim3 blk(16, 16);
    qproj_kernel<<<dim3(CMODEL / 64, (2 * HW) / 128), blk>>>(hs, Wq);
    kvproj_kernel<<<dim3(CMODEL / 64, (NB * LSEQ + 63) / 64), blk>>>(ehs, Wk, Wv);

    att_kernel<<<dim3(HW / 128, HEADS, NB), 128>>>();

    reduce9_kernel<<<(HW * CMODEL / 4) / 256, 256>>>();

    outproj_kernel<<<dim3(CMODEL / 64, (2 * HW) / 128), blk>>>(Wo, bo, out);
}

// round 10
// speedup vs baseline: 1.4756x; 1.2071x over previous
#include <cuda_runtime.h>
#include <math.h>

#define HEADS 8
#define DHEAD 40
#define CMODEL 320
#define CX 768
#define LSEQ 77
#define NB 10
#define HW 4096
#define NPHASE 9

typedef unsigned long long u64;

// ---------------- packed f32x2 helpers (FFMA2 path, sm_100+) ---------------
__device__ __forceinline__ u64 pack2(float lo, float hi) {
    u64 r; asm("mov.b64 %0, {%1, %2};" : "=l"(r) : "f"(lo), "f"(hi)); return r;
}
__device__ __forceinline__ float2 unpk2(u64 v) {
    float2 f; asm("mov.b64 {%0, %1}, %2;" : "=f"(f.x), "=f"(f.y) : "l"(v)); return f;
}
__device__ __forceinline__ u64 ffma2(u64 a, u64 b, u64 c) {
    u64 d; asm("fma.rn.f32x2 %0, %1, %2, %3;" : "=l"(d) : "l"(a), "l"(b), "l"(c)); return d;
}

// ---------------- scratch (device globals; no allocation allowed) ----------
__device__ __align__(16) float g_q[2 * HW * CMODEL];
__device__ __align__(16) float g_k[NB * LSEQ * CMODEL];
__device__ __align__(16) float g_v[NB * LSEQ * CMODEL];
__device__ __align__(16) float g_A[2 * HW * CMODEL];      // [0:HW)=uncond, [HW:2HW)=weighted sum
__device__ __align__(16) float g_O[NPHASE * HW * CMODEL]; // per-batch weighted outputs (b=1..9)
__device__ __align__(16) float g_w9[NPHASE * HW];
__device__ __align__(16) float g_wsum[HW];

// ---------------- phase weights (jax.image.resize bilinear+antialias) ------
__device__ __forceinline__ float resize_factor(int o, float lo, float hi) {
    float sf = (o + 0.5f) * 8.0f - 0.5f;
    float num = 0.f, den = 0.f;
    int h0 = o * 8 - 4, h1 = o * 8 + 11;
    #pragma unroll 1
    for (int h = h0; h <= h1; ++h) {
        if (h < 0 || h > 511) continue;
        float fh = (float)h;
        float wgt = 1.0f - fabsf(fh - sf) * 0.125f;
        den += wgt;
        if (fh >= lo && fh < hi) num += wgt;
    }
    return num / den;
}

__global__ void weights_kernel(const float* __restrict__ bboxes) {
    int p = blockIdx.x * blockDim.x + threadIdx.x;
    if (p >= HW) return;
    int r = p >> 6, c = p & 63;
    float s = 0.1f;
    g_w9[p] = 0.1f;
    #pragma unroll 1
    for (int i = 0; i < 8; ++i) {
        float x0 = bboxes[i * 4 + 0], y0 = bboxes[i * 4 + 1];
        float x1 = bboxes[i * 4 + 2], y1 = bboxes[i * 4 + 3];
        float wmin = floorf(512.f * x0), wmax = floorf(512.f * x1);
        float hmin = floorf(512.f * y0), hmax = floorf(512.f * y1);
        float wv = 10.f * resize_factor(r, hmin, hmax) * resize_factor(c, wmin, wmax);
        g_w9[(i + 1) * HW + p] = wv;
        s += wv;
    }
    g_wsum[p] = s;
}

// ---------------- fused K+V projection: 64x64 tile, FFMA2 row-pairs --------
__global__ void __launch_bounds__(256) kvproj_kernel(
    const float* __restrict__ ehs,
    const float* __restrict__ Wk, const float* __restrict__ Wv)
{
    __shared__ __align__(16) float As[16][72];
    __shared__ __align__(16) float Bk[16][64];
    __shared__ __align__(16) float Bv[16][64];
    const int tx = threadIdx.x, ty = threadIdx.y;
    const int t  = ty * 16 + tx;
    const int row0 = blockIdx.y * 64, col0 = blockIdx.x * 64;
    const int li = t >> 2, lk = (t & 3) << 2;
    const int bk = t >> 4, bj = (t & 15) << 2;

    u64 ak[2][4], av[2][4];
    #pragma unroll
    for (int i = 0; i < 2; ++i)
        #pragma unroll
        for (int j = 0; j < 4; ++j) { ak[i][j] = 0ULL; av[i][j] = 0ULL; }

    for (int k0 = 0; k0 < CX; k0 += 16) {
        // rows up to 831 < 847 total in ehs — unguarded load is safe
        float4 a = *(const float4*)(ehs + (size_t)(row0 + li) * CX + k0 + lk);
        As[lk + 0][li] = a.x; As[lk + 1][li] = a.y;
        As[lk + 2][li] = a.z; As[lk + 3][li] = a.w;
        *(float4*)(&Bk[bk][bj]) = *(const float4*)(Wk + (size_t)(k0 + bk) * CMODEL + col0 + bj);
        *(float4*)(&Bv[bk][bj]) = *(const float4*)(Wv + (size_t)(k0 + bk) * CMODEL + col0 + bj);
        __syncthreads();
        #pragma unroll
        for (int kk = 0; kk < 16; ++kk) {
            ulonglong2 ap = *(const ulonglong2*)(&As[kk][ty * 4]);  // row pairs (0,1),(2,3)
            float4 b1 = *(const float4*)(&Bk[kk][tx * 4]);
            float4 b2 = *(const float4*)(&Bv[kk][tx * 4]);
            u64 k0s = pack2(b1.x, b1.x), k1s = pack2(b1.y, b1.y);
            u64 k2s = pack2(b1.z, b1.z), k3s = pack2(b1.w, b1.w);
            u64 v0s = pack2(b2.x, b2.x), v1s = pack2(b2.y, b2.y);
            u64 v2s = pack2(b2.z, b2.z), v3s = pack2(b2.w, b2.w);
            ak[0][0] = ffma2(ap.x, k0s, ak[0][0]); ak[0][1] = ffma2(ap.x, k1s, ak[0][1]);
            ak[0][2] = ffma2(ap.x, k2s, ak[0][2]); ak[0][3] = ffma2(ap.x, k3s, ak[0][3]);
            ak[1][0] = ffma2(ap.y, k0s, ak[1][0]); ak[1][1] = ffma2(ap.y, k1s, ak[1][1]);
            ak[1][2] = ffma2(ap.y, k2s, ak[1][2]); ak[1][3] = ffma2(ap.y, k3s, ak[1][3]);
            av[0][0] = ffma2(ap.x, v0s, av[0][0]); av[0][1] = ffma2(ap.x, v1s, av[0][1]);
            av[0][2] = ffma2(ap.x, v2s, av[0][2]); av[0][3] = ffma2(ap.x, v3s, av[0][3]);
            av[1][0] = ffma2(ap.y, v0s, av[1][0]); av[1][1] = ffma2(ap.y, v1s, av[1][1]);
            av[1][2] = ffma2(ap.y, v2s, av[1][2]); av[1][3] = ffma2(ap.y, v3s, av[1][3]);
        }
        __syncthreads();
    }
    #pragma unroll
    for (int i = 0; i < 2; ++i) {
        float2 c0 = unpk2(ak[i][0]), c1 = unpk2(ak[i][1]);
        float2 c2 = unpk2(ak[i][2]), c3 = unpk2(ak[i][3]);
        float2 d0 = unpk2(av[i][0]), d1 = unpk2(av[i][1]);
        float2 d2 = unpk2(av[i][2]), d3 = unpk2(av[i][3]);
        int re = row0 + ty * 4 + 2 * i;
        if (re < NB * LSEQ) {
            *(float4*)(g_k + (size_t)re * CMODEL + col0 + tx * 4) = make_float4(c0.x, c1.x, c2.x, c3.x);
            *(float4*)(g_v + (size_t)re * CMODEL + col0 + tx * 4) = make_float4(d0.x, d1.x, d2.x, d3.x);
        }
        if (re + 1 < NB * LSEQ) {
            *(float4*)(g_k + (size_t)(re + 1) * CMODEL + col0 + tx * 4) = make_float4(c0.y, c1.y, c2.y, c3.y);
            *(float4*)(g_v + (size_t)(re + 1) * CMODEL + col0 + tx * 4) = make_float4(d0.y, d1.y, d2.y, d3.y);
        }
    }
}

// ---------------- 128x64 tile GEMM core, FFMA2 row-pair micro --------------
__device__ __forceinline__ void gemm128_f2(
    const float* __restrict__ A, const float* __restrict__ B,
    int K, int N, u64 (&acc)[4][4])
{
    __shared__ __align__(16) float As[16][132];
    __shared__ __align__(16) float Bs[16][64];
    const int tx = threadIdx.x, ty = threadIdx.y;
    const int t  = ty * 16 + tx;
    const int row0 = blockIdx.y * 128, col0 = blockIdx.x * 64;
    const int li = t >> 1, lk = (t & 1) << 3;
    const int bk = t >> 4, bj = (t & 15) << 2;

    #pragma unroll
    for (int i = 0; i < 4; ++i)
        #pragma unroll
        for (int j = 0; j < 4; ++j) acc[i][j] = 0ULL;

    for (int k0 = 0; k0 < K; k0 += 16) {
        const float* ap = A + (size_t)(row0 + li) * K + k0 + lk;
        float4 a0 = *(const float4*)(ap);
        float4 a1 = *(const float4*)(ap + 4);
        As[lk + 0][li] = a0.x; As[lk + 1][li] = a0.y;
        As[lk + 2][li] = a0.z; As[lk + 3][li] = a0.w;
        As[lk + 4][li] = a1.x; As[lk + 5][li] = a1.y;
        As[lk + 6][li] = a1.z; As[lk + 7][li] = a1.w;
        *(float4*)(&Bs[bk][bj]) = *(const float4*)(B + (size_t)(k0 + bk) * N + col0 + bj);
        __syncthreads();
        #pragma unroll
        for (int kk = 0; kk < 16; ++kk) {
            const ulonglong2* ar = (const ulonglong2*)(&As[kk][ty * 8]);
            ulonglong2 alo = ar[0], ahi = ar[1];   // row pairs (0,1),(2,3),(4,5),(6,7)
            float4 b = *(const float4*)(&Bs[kk][tx * 4]);
            u64 b0 = pack2(b.x, b.x), b1 = pack2(b.y, b.y);
            u64 b2 = pack2(b.z, b.z), b3 = pack2(b.w, b.w);
            acc[0][0] = ffma2(alo.x, b0, acc[0][0]); acc[0][1] = ffma2(alo.x, b1, acc[0][1]);
            acc[0][2] = ffma2(alo.x, b2, acc[0][2]); acc[0][3] = ffma2(alo.x, b3, acc[0][3]);
            acc[1][0] = ffma2(alo.y, b0, acc[1][0]); acc[1][1] = ffma2(alo.y, b1, acc[1][1]);
            acc[1][2] = ffma2(alo.y, b2, acc[1][2]); acc[1][3] = ffma2(alo.y, b3, acc[1][3]);
            acc[2][0] = ffma2(ahi.x, b0, acc[2][0]); acc[2][1] = ffma2(ahi.x, b1, acc[2][1]);
            acc[2][2] = ffma2(ahi.x, b2, acc[2][2]); acc[2][3] = ffma2(ahi.x, b3, acc[2][3]);
            acc[3][0] = ffma2(ahi.y, b0, acc[3][0]); acc[3][1] = ffma2(ahi.y, b1, acc[3][1]);
            acc[3][2] = ffma2(ahi.y, b2, acc[3][2]); acc[3][3] = ffma2(ahi.y, b3, acc[3][3]);
        }
        __syncthreads();
    }
}

// Q projection: [8192,320] x [320,320] -> g_q
__global__ void __launch_bounds__(256) qproj_kernel(
    const float* __restrict__ hs, const float* __restrict__ Wq)
{
    u64 acc[4][4];
    gemm128_f2(hs, Wq, CMODEL, CMODEL, acc);
    const int row0 = blockIdx.y * 128, col0 = blockIdx.x * 64;
    const int tx = threadIdx.x, ty = threadIdx.y;
    #pragma unroll
    for (int i = 0; i < 4; ++i) {
        float2 c0 = unpk2(acc[i][0]), c1 = unpk2(acc[i][1]);
        float2 c2 = unpk2(acc[i][2]), c3 = unpk2(acc[i][3]);
        int re = row0 + ty * 8 + 2 * i;
        *(float4*)(g_q + (size_t)re * CMODEL + col0 + tx * 4) = make_float4(c0.x, c1.x, c2.x, c3.x);
        *(float4*)(g_q + (size_t)(re + 1) * CMODEL + col0 + tx * 4) = make_float4(c0.y, c1.y, c2.y, c3.y);
    }
}

// Output projection + fused epilogue
__global__ void __launch_bounds__(256) outproj_kernel(
    const float* __restrict__ Wo, const float* __restrict__ bo,
    float* __restrict__ out)
{
    u64 acc[4][4];
    gemm128_f2(g_A, Wo, CMODEL, CMODEL, acc);
    const int row0 = blockIdx.y * 128, col0 = blockIdx.x * 64;
    const int tx = threadIdx.x, ty = threadIdx.y;
    const int c0i = col0 + tx * 4;
    float b0 = bo[c0i + 0], b1 = bo[c0i + 1], b2 = bo[c0i + 2], b3 = bo[c0i + 3];
    #pragma unroll
    for (int i = 0; i < 4; ++i) {
        float2 c0 = unpk2(acc[i][0]), c1 = unpk2(acc[i][1]);
        float2 c2 = unpk2(acc[i][2]), c3 = unpk2(acc[i][3]);
        float vals[2][4] = {{c0.x, c1.x, c2.x, c3.x}, {c0.y, c1.y, c2.y, c3.y}};
        #pragma unroll
        for (int h = 0; h < 2; ++h) {
            int r = row0 + ty * 8 + 2 * i + h;
            float4 o;
            if (r < HW) {
                o = make_float4(vals[h][0] + b0, vals[h][1] + b1,
                                vals[h][2] + b2, vals[h][3] + b3);
            } else {
                float ws = g_wsum[r - HW];
                float invD = 1.f / (ws + 1e-6f);
                float bs = ws * invD;
                o = make_float4(vals[h][0] * invD + b0 * bs,
                                vals[h][1] * invD + b1 * bs,
                                vals[h][2] * invD + b2 * bs,
                                vals[h][3] * invD + b3 * bs);
            }
            *(float4*)(out + (size_t)r * CMODEL + c0i) = o;
        }
    }
}

// ---------------- attention: one (q-tile, head, batch) per block -----------
// Zero-weight skip: for b>=1, pixels outside the bbox's bilinear footprint
// have g_w9 == 0 exactly -> their contribution is exactly 0. Skip the whole
// block when no thread has weight; skip per-thread at boundaries.
__global__ void __launch_bounds__(128) att_kernel()
{
    __shared__ __align__(16) u64 ks[LSEQ * 20];   // 77 rows x 40 floats (20 u64)
    __shared__ __align__(16) u64 vs[LSEQ * 20];
    const int head = blockIdx.y;
    const int b = blockIdx.z;
    const int t = threadIdx.x;
    const int p = blockIdx.x * 128 + t;
    const float scale = 0.15811388300841897f;     // 1/sqrt(40)

    float wg = 1.f;
    float* optr;
    if (b == 0) {
        optr = g_A + (size_t)p * CMODEL + head * DHEAD;
    } else {
        wg = g_w9[(b - 1) * HW + p];
        optr = g_O + ((size_t)(b - 1) * HW + p) * CMODEL + head * DHEAD;
    }
    float4* o4 = (float4*)optr;

    // whole-block skip (common case: bbox rectangles cover ~15% of pixels)
    int any = __syncthreads_count(wg != 0.f);
    if (any == 0) {
        float4 z = make_float4(0.f, 0.f, 0.f, 0.f);
        #pragma unroll
        for (int d = 0; d < 10; ++d) o4[d] = z;
        return;
    }

    // stage K/V head tile (16B vectors; CMODEL row = 80 ulonglong2)
    {
        const ulonglong2* gk = (const ulonglong2*)g_k;
        const ulonglong2* gv = (const ulonglong2*)g_v;
        ulonglong2* ks2 = (ulonglong2*)ks;
        ulonglong2* vs2 = (ulonglong2*)vs;
        for (int idx = t; idx < LSEQ * 10; idx += 128) {
            int j = idx / 10, d = idx - j * 10;
            int g = (b * LSEQ + j) * 80 + head * 10 + d;
            ks2[idx] = gk[g];
            vs2[idx] = gv[g];
        }
    }
    __syncthreads();

    // per-thread skip (boundary blocks); no further barriers below
    if (wg == 0.f) {
        float4 z = make_float4(0.f, 0.f, 0.f, 0.f);
        #pragma unroll
        for (int d = 0; d < 10; ++d) o4[d] = z;
        return;
    }

    // load q row (packed pairs)
    u64 q2[20];
    {
        int qb = (b == 0) ? 0 : 1;
        const ulonglong2* qp = (const ulonglong2*)(g_q + ((size_t)qb * HW + p) * CMODEL + head * DHEAD);
        #pragma unroll
        for (int d = 0; d < 10; ++d) {
            ulonglong2 qq = qp[d];
            q2[2 * d] = qq.x; q2[2 * d + 1] = qq.y;
        }
    }

    u64 acc2[20];
    #pragma unroll
    for (int d = 0; d < 20; ++d) acc2[d] = 0ULL;
    float l = 0.f;

    // single-pass softmax (no max subtraction: |scores| <~ 1.5, safe in fp32)
    #pragma unroll 1
    for (int j = 0; j < LSEQ; ++j) {
        const ulonglong2* kj = (const ulonglong2*)(ks + j * 20);
        u64 sA = 0ULL, sB = 0ULL;
        #pragma unroll
        for (int d = 0; d < 10; ++d) {
            ulonglong2 kk = kj[d];
            sA = ffma2(q2[2 * d], kk.x, sA);
            sB = ffma2(q2[2 * d + 1], kk.y, sB);
        }
        float2 fa = unpk2(sA), fb = unpk2(sB);
        float s = ((fa.x + fa.y) + (fb.x + fb.y)) * scale;
        float pe = __expf(s);
        l += pe;
        u64 pe2 = pack2(pe, pe);
        const ulonglong2* vj = (const ulonglong2*)(vs + j * 20);
        #pragma unroll
        for (int d = 0; d < 10; ++d) {
            ulonglong2 vv = vj[d];
            acc2[2 * d]     = ffma2(pe2, vv.x, acc2[2 * d]);
            acc2[2 * d + 1] = ffma2(pe2, vv.y, acc2[2 * d + 1]);
        }
    }

    float inv = 1.f / l;
    float sc = (b == 0) ? inv : wg * inv;   // pre-weighted; reduce kernel just sums
    #pragma unroll
    for (int d = 0; d < 10; ++d) {
        float2 x = unpk2(acc2[2 * d]);
        float2 y = unpk2(acc2[2 * d + 1]);
        o4[d] = make_float4(x.x * sc, x.y * sc, y.x * sc, y.y * sc);
    }
}

// ---------------- sum the 9 pre-weighted batch outputs (w-aware) -----------
__global__ void __launch_bounds__(256) reduce9_kernel()
{
    int idx = blockIdx.x * 256 + threadIdx.x;   // over HW*CMODEL/4 float4s
    int p = idx / (CMODEL / 4);                 // pixel of this float4
    const float4* o4 = (const float4*)g_O;
    const size_t stride = (size_t)HW * CMODEL / 4;
    float4 s = make_float4(0.f, 0.f, 0.f, 0.f);
    #pragma unroll
    for (int bb = 0; bb < NPHASE; ++bb) {
        if (g_w9[bb * HW + p] != 0.f) {         // skip exactly-zero rows (~85%)
            float4 v = o4[bb * stride + idx];
            s.x += v.x; s.y += v.y; s.z += v.z; s.w += v.w;
        }
    }
    ((float4*)(g_A + (size_t)HW * CMODEL))[idx] = s;
}

// ---------------- launch ---------------------------------------------------
extern "C" void kernel_launch(void* const* d_in, const int* in_sizes, int n_in,
                              void* d_out, int out_size)
{
    (void)in_sizes; (void)n_in; (void)out_size;
    const float* hs  = (const float*)d_in[0];
    const float* ehs = (const float*)d_in[1];
    const float* bb  = (const float*)d_in[2];
    const float* Wq  = (const float*)d_in[3];
    const float* Wk  = (const float*)d_in[4];
    const float* Wv  = (const float*)d_in[5];
    const float* Wo  = (const float*)d_in[6];
    const float* bo  = (const float*)d_in[7];
    float* out = (float*)d_out;

    weights_kernel<<<16, 256>>>(bb);

    dim3 blk(16, 16);
    qproj_kernel<<<dim3(CMODEL / 64, (2 * HW) / 128), blk>>>(hs, Wq);
    kvproj_kernel<<<dim3(CMODEL / 64, (NB * LSEQ + 63) / 64), blk>>>(ehs, Wk, Wv);

    att_kernel<<<dim3(HW / 128, HEADS, NB), 128>>>();

    reduce9_kernel<<<(HW * CMODEL / 4) / 256, 256>>>();

    outproj_kernel<<<dim3(CMODEL / 64, (2 * HW) / 128), blk>>>(Wo, bo, out);
}

// round 12
// speedup vs baseline: 1.6618x; 1.1262x over previous
#include <cuda_runtime.h>
#include <math.h>

#define HEADS 8
#define DHEAD 40
#define CMODEL 320
#define CX 768
#define LSEQ 77
#define NB 10
#define HW 4096
#define NPHASE 9

typedef unsigned long long u64;

// ---------------- packed f32x2 helpers (FFMA2 path, sm_100+) ---------------
__device__ __forceinline__ u64 pack2(float lo, float hi) {
    u64 r; asm("mov.b64 %0, {%1, %2};" : "=l"(r) : "f"(lo), "f"(hi)); return r;
}
__device__ __forceinline__ float2 unpk2(u64 v) {
    float2 f; asm("mov.b64 {%0, %1}, %2;" : "=f"(f.x), "=f"(f.y) : "l"(v)); return f;
}
__device__ __forceinline__ u64 ffma2(u64 a, u64 b, u64 c) {
    u64 d; asm("fma.rn.f32x2 %0, %1, %2, %3;" : "=l"(d) : "l"(a), "l"(b), "l"(c)); return d;
}

// ---------------- scratch (device globals; no allocation allowed) ----------
__device__ __align__(16) float g_q[2 * HW * CMODEL];
__device__ __align__(16) float g_k[NB * LSEQ * CMODEL];
__device__ __align__(16) float g_v[NB * LSEQ * CMODEL];
__device__ __align__(16) float g_A[2 * HW * CMODEL];      // [0:HW)=uncond, [HW:2HW)=weighted sum
__device__ __align__(16) float g_O[NPHASE * HW * CMODEL]; // per-batch weighted outputs (b=1..9)
__device__ __align__(16) float g_w9[NPHASE * HW];
__device__ __align__(16) float g_wsum[HW];

// ---------------- phase weights (jax.image.resize bilinear+antialias) ------
__device__ __forceinline__ float resize_factor(int o, float lo, float hi) {
    float sf = (o + 0.5f) * 8.0f - 0.5f;
    float num = 0.f, den = 0.f;
    int h0 = o * 8 - 4, h1 = o * 8 + 11;
    #pragma unroll 1
    for (int h = h0; h <= h1; ++h) {
        if (h < 0 || h > 511) continue;
        float fh = (float)h;
        float wgt = 1.0f - fabsf(fh - sf) * 0.125f;
        den += wgt;
        if (fh >= lo && fh < hi) num += wgt;
    }
    return num / den;
}

__global__ void weights_kernel(const float* __restrict__ bboxes) {
    int p = blockIdx.x * blockDim.x + threadIdx.x;
    if (p >= HW) return;
    int r = p >> 6, c = p & 63;
    float s = 0.1f;
    g_w9[p] = 0.1f;
    #pragma unroll 1
    for (int i = 0; i < 8; ++i) {
        float x0 = bboxes[i * 4 + 0], y0 = bboxes[i * 4 + 1];
        float x1 = bboxes[i * 4 + 2], y1 = bboxes[i * 4 + 3];
        float wmin = floorf(512.f * x0), wmax = floorf(512.f * x1);
        float hmin = floorf(512.f * y0), hmax = floorf(512.f * y1);
        float wv = 10.f * resize_factor(r, hmin, hmax) * resize_factor(c, wmin, wmax);
        g_w9[(i + 1) * HW + p] = wv;
        s += wv;
    }
    g_wsum[p] = s;
}

// ---------------- fused K+V projection: 32x64 tile (125 blocks) ------------
__global__ void __launch_bounds__(256) kvproj_kernel(
    const float* __restrict__ ehs,
    const float* __restrict__ Wk, const float* __restrict__ Wv)
{
    __shared__ __align__(16) float As[16][36];
    __shared__ __align__(16) float Bk[16][64];
    __shared__ __align__(16) float Bv[16][64];
    const int tx = threadIdx.x, ty = threadIdx.y;
    const int t  = ty * 16 + tx;
    const int row0 = blockIdx.y * 32, col0 = blockIdx.x * 64;
    const int li = t >> 3, lk = (t & 7) << 1;    // A: 32 rows x 16 k, float2 each
    const int bk = t >> 4, bj = (t & 15) << 2;

    u64 ak[4], av[4];
    #pragma unroll
    for (int j = 0; j < 4; ++j) { ak[j] = 0ULL; av[j] = 0ULL; }

    for (int k0 = 0; k0 < CX; k0 += 16) {
        // rows up to 799 < 847 total in ehs — unguarded load is safe
        float2 a = *(const float2*)(ehs + (size_t)(row0 + li) * CX + k0 + lk);
        As[lk + 0][li] = a.x; As[lk + 1][li] = a.y;
        *(float4*)(&Bk[bk][bj]) = *(const float4*)(Wk + (size_t)(k0 + bk) * CMODEL + col0 + bj);
        *(float4*)(&Bv[bk][bj]) = *(const float4*)(Wv + (size_t)(k0 + bk) * CMODEL + col0 + bj);
        __syncthreads();
        #pragma unroll
        for (int kk = 0; kk < 16; ++kk) {
            u64 ap = *(const u64*)(&As[kk][ty * 2]);   // row pair (2ty, 2ty+1)
            float4 b1 = *(const float4*)(&Bk[kk][tx * 4]);
            float4 b2 = *(const float4*)(&Bv[kk][tx * 4]);
            ak[0] = ffma2(ap, pack2(b1.x, b1.x), ak[0]);
            ak[1] = ffma2(ap, pack2(b1.y, b1.y), ak[1]);
            ak[2] = ffma2(ap, pack2(b1.z, b1.z), ak[2]);
            ak[3] = ffma2(ap, pack2(b1.w, b1.w), ak[3]);
            av[0] = ffma2(ap, pack2(b2.x, b2.x), av[0]);
            av[1] = ffma2(ap, pack2(b2.y, b2.y), av[1]);
            av[2] = ffma2(ap, pack2(b2.z, b2.z), av[2]);
            av[3] = ffma2(ap, pack2(b2.w, b2.w), av[3]);
        }
        __syncthreads();
    }
    float2 c0 = unpk2(ak[0]), c1 = unpk2(ak[1]), c2 = unpk2(ak[2]), c3 = unpk2(ak[3]);
    float2 d0 = unpk2(av[0]), d1 = unpk2(av[1]), d2 = unpk2(av[2]), d3 = unpk2(av[3]);
    int re = row0 + ty * 2;
    if (re < NB * LSEQ) {
        *(float4*)(g_k + (size_t)re * CMODEL + col0 + tx * 4) = make_float4(c0.x, c1.x, c2.x, c3.x);
        *(float4*)(g_v + (size_t)re * CMODEL + col0 + tx * 4) = make_float4(d0.x, d1.x, d2.x, d3.x);
    }
    if (re + 1 < NB * LSEQ) {
        *(float4*)(g_k + (size_t)(re + 1) * CMODEL + col0 + tx * 4) = make_float4(c0.y, c1.y, c2.y, c3.y);
        *(float4*)(g_v + (size_t)(re + 1) * CMODEL + col0 + tx * 4) = make_float4(d0.y, d1.y, d2.y, d3.y);
    }
}

// ---------------- 128x64 GEMM core, 8x8 micro, block (8,16) = 128 thr ------
// Thread (tx,ty): rows ty*8..ty*8+7 (4 pairs), cols col0+{tx*4..+3, 32+tx*4..+3}.
// 16 ty x 8 rows = 128 rows; 8 tx x 8 cols = 64 cols — exact tile coverage.
// Per kk: 4 LDS.128 + 8 pack2 + 32 ffma2 (64 FMA lanes).
__device__ __forceinline__ void gemm128_f2(
    const float* __restrict__ A, const float* __restrict__ B,
    int K, int N, u64 (&acc)[4][8])
{
    __shared__ __align__(16) float As[16][132];
    __shared__ __align__(16) float Bs[16][64];
    const int tx = threadIdx.x, ty = threadIdx.y;   // tx 0..7, ty 0..15
    const int t  = ty * 8 + tx;                     // 0..127
    const int row0 = blockIdx.y * 128, col0 = blockIdx.x * 64;
    const int bk = t >> 3, bj = (t & 7) << 3;       // B: 16 k-rows x 64 cols, 8 floats/thr

    #pragma unroll
    for (int i = 0; i < 4; ++i)
        #pragma unroll
        for (int j = 0; j < 8; ++j) acc[i][j] = 0ULL;

    for (int k0 = 0; k0 < K; k0 += 16) {
        // A: each thread loads the full 16-float k-slice of its row t
        const float* ap = A + (size_t)(row0 + t) * K + k0;
        #pragma unroll
        for (int j = 0; j < 4; ++j) {
            float4 a = *(const float4*)(ap + 4 * j);
            As[4 * j + 0][t] = a.x; As[4 * j + 1][t] = a.y;
            As[4 * j + 2][t] = a.z; As[4 * j + 3][t] = a.w;
        }
        // B: 8 floats per thread
        *(float4*)(&Bs[bk][bj])     = *(const float4*)(B + (size_t)(k0 + bk) * N + col0 + bj);
        *(float4*)(&Bs[bk][bj + 4]) = *(const float4*)(B + (size_t)(k0 + bk) * N + col0 + bj + 4);
        __syncthreads();
        #pragma unroll
        for (int kk = 0; kk < 16; ++kk) {
            const ulonglong2* ar = (const ulonglong2*)(&As[kk][ty * 8]);
            ulonglong2 aA = ar[0], aB = ar[1];   // row pairs (0,1),(2,3),(4,5),(6,7)
            float4 blo = *(const float4*)(&Bs[kk][tx * 4]);        // cols 0..31 half
            float4 bhi = *(const float4*)(&Bs[kk][32 + tx * 4]);   // cols 32..63 half
            u64 s0 = pack2(blo.x, blo.x), s1 = pack2(blo.y, blo.y);
            u64 s2 = pack2(blo.z, blo.z), s3 = pack2(blo.w, blo.w);
            u64 s4 = pack2(bhi.x, bhi.x), s5 = pack2(bhi.y, bhi.y);
            u64 s6 = pack2(bhi.z, bhi.z), s7 = pack2(bhi.w, bhi.w);
            acc[0][0] = ffma2(aA.x, s0, acc[0][0]); acc[0][1] = ffma2(aA.x, s1, acc[0][1]);
            acc[0][2] = ffma2(aA.x, s2, acc[0][2]); acc[0][3] = ffma2(aA.x, s3, acc[0][3]);
            acc[0][4] = ffma2(aA.x, s4, acc[0][4]); acc[0][5] = ffma2(aA.x, s5, acc[0][5]);
            acc[0][6] = ffma2(aA.x, s6, acc[0][6]); acc[0][7] = ffma2(aA.x, s7, acc[0][7]);
            acc[1][0] = ffma2(aA.y, s0, acc[1][0]); acc[1][1] = ffma2(aA.y, s1, acc[1][1]);
            acc[1][2] = ffma2(aA.y, s2, acc[1][2]); acc[1][3] = ffma2(aA.y, s3, acc[1][3]);
            acc[1][4] = ffma2(aA.y, s4, acc[1][4]); acc[1][5] = ffma2(aA.y, s5, acc[1][5]);
            acc[1][6] = ffma2(aA.y, s6, acc[1][6]); acc[1][7] = ffma2(aA.y, s7, acc[1][7]);
            acc[2][0] = ffma2(aB.x, s0, acc[2][0]); acc[2][1] = ffma2(aB.x, s1, acc[2][1]);
            acc[2][2] = ffma2(aB.x, s2, acc[2][2]); acc[2][3] = ffma2(aB.x, s3, acc[2][3]);
            acc[2][4] = ffma2(aB.x, s4, acc[2][4]); acc[2][5] = ffma2(aB.x, s5, acc[2][5]);
            acc[2][6] = ffma2(aB.x, s6, acc[2][6]); acc[2][7] = ffma2(aB.x, s7, acc[2][7]);
            acc[3][0] = ffma2(aB.y, s0, acc[3][0]); acc[3][1] = ffma2(aB.y, s1, acc[3][1]);
            acc[3][2] = ffma2(aB.y, s2, acc[3][2]); acc[3][3] = ffma2(aB.y, s3, acc[3][3]);
            acc[3][4] = ffma2(aB.y, s4, acc[3][4]); acc[3][5] = ffma2(aB.y, s5, acc[3][5]);
            acc[3][6] = ffma2(aB.y, s6, acc[3][6]); acc[3][7] = ffma2(aB.y, s7, acc[3][7]);
        }
        __syncthreads();
    }
}

// Q projection: [8192,320] x [320,320] -> g_q
__global__ void __launch_bounds__(128) qproj_kernel(
    const float* __restrict__ hs, const float* __restrict__ Wq)
{
    u64 acc[4][8];
    gemm128_f2(hs, Wq, CMODEL, CMODEL, acc);
    const int row0 = blockIdx.y * 128, col0 = blockIdx.x * 64;
    const int tx = threadIdx.x, ty = threadIdx.y;
    #pragma unroll
    for (int i = 0; i < 4; ++i) {
        float2 p[8];
        #pragma unroll
        for (int j = 0; j < 8; ++j) p[j] = unpk2(acc[i][j]);
        int re = row0 + ty * 8 + 2 * i;
        float* r0 = g_q + (size_t)re * CMODEL + col0;
        float* r1 = r0 + CMODEL;
        *(float4*)(r0 + tx * 4)      = make_float4(p[0].x, p[1].x, p[2].x, p[3].x);
        *(float4*)(r0 + 32 + tx * 4) = make_float4(p[4].x, p[5].x, p[6].x, p[7].x);
        *(float4*)(r1 + tx * 4)      = make_float4(p[0].y, p[1].y, p[2].y, p[3].y);
        *(float4*)(r1 + 32 + tx * 4) = make_float4(p[4].y, p[5].y, p[6].y, p[7].y);
    }
}

// Output projection + fused epilogue
__global__ void __launch_bounds__(128) outproj_kernel(
    const float* __restrict__ Wo, const float* __restrict__ bo,
    float* __restrict__ out)
{
    u64 acc[4][8];
    gemm128_f2(g_A, Wo, CMODEL, CMODEL, acc);
    const int row0 = blockIdx.y * 128, col0 = blockIdx.x * 64;
    const int tx = threadIdx.x, ty = threadIdx.y;
    const int cA = col0 + tx * 4, cB = col0 + 32 + tx * 4;
    float4 bA = *(const float4*)(bo + cA);
    float4 bB = *(const float4*)(bo + cB);
    #pragma unroll
    for (int i = 0; i < 4; ++i) {
        float2 p[8];
        #pragma unroll
        for (int j = 0; j < 8; ++j) p[j] = unpk2(acc[i][j]);
        #pragma unroll
        for (int h = 0; h < 2; ++h) {
            int r = row0 + ty * 8 + 2 * i + h;
            float v0 = h ? p[0].y : p[0].x, v1 = h ? p[1].y : p[1].x;
            float v2 = h ? p[2].y : p[2].x, v3 = h ? p[3].y : p[3].x;
            float v4 = h ? p[4].y : p[4].x, v5 = h ? p[5].y : p[5].x;
            float v6 = h ? p[6].y : p[6].x, v7 = h ? p[7].y : p[7].x;
            float4 oA, oB;
            if (r < HW) {
                oA = make_float4(v0 + bA.x, v1 + bA.y, v2 + bA.z, v3 + bA.w);
                oB = make_float4(v4 + bB.x, v5 + bB.y, v6 + bB.z, v7 + bB.w);
            } else {
                float ws = g_wsum[r - HW];
                float invD = 1.f / (ws + 1e-6f);
                float bs = ws * invD;
                oA = make_float4(v0 * invD + bA.x * bs, v1 * invD + bA.y * bs,
                                 v2 * invD + bA.z * bs, v3 * invD + bA.w * bs);
                oB = make_float4(v4 * invD + bB.x * bs, v5 * invD + bB.y * bs,
                                 v6 * invD + bB.z * bs, v7 * invD + bB.w * bs);
            }
            *(float4*)(out + (size_t)r * CMODEL + cA) = oA;
            *(float4*)(out + (size_t)r * CMODEL + cB) = oB;
        }
    }
}

// ---------------- attention: one (q-tile, head, batch) per block -----------
// Zero-weight skip WITHOUT zero writes: reduce9 skips w==0 rows, so skipped
// (batch,pixel) rows of g_O are never read — just return.
__global__ void __launch_bounds__(128) att_kernel()
{
    __shared__ __align__(16) u64 ks[LSEQ * 20];   // 77 rows x 40 floats (20 u64)
    __shared__ __align__(16) u64 vs[LSEQ * 20];
    const int head = blockIdx.y;
    const int b = blockIdx.z;
    const int t = threadIdx.x;
    const int p = blockIdx.x * 128 + t;
    const float scale = 0.15811388300841897f;     // 1/sqrt(40)

    float wg = 1.f;
    float* optr;
    if (b == 0) {
        optr = g_A + (size_t)p * CMODEL + head * DHEAD;
    } else {
        wg = g_w9[(b - 1) * HW + p];
        optr = g_O + ((size_t)(b - 1) * HW + p) * CMODEL + head * DHEAD;
    }
    float4* o4 = (float4*)optr;

    // whole-block skip (common case: bbox rectangles cover ~15% of pixels)
    int any = __syncthreads_count(wg != 0.f);
    if (any == 0) return;

    // stage K/V head tile (16B vectors; CMODEL row = 80 ulonglong2)
    {
        const ulonglong2* gk = (const ulonglong2*)g_k;
        const ulonglong2* gv = (const ulonglong2*)g_v;
        ulonglong2* ks2 = (ulonglong2*)ks;
        ulonglong2* vs2 = (ulonglong2*)vs;
        for (int idx = t; idx < LSEQ * 10; idx += 128) {
            int j = idx / 10, d = idx - j * 10;
            int g = (b * LSEQ + j) * 80 + head * 10 + d;
            ks2[idx] = gk[g];
            vs2[idx] = gv[g];
        }
    }
    __syncthreads();

    // per-thread skip (boundary blocks); no further barriers below
    if (wg == 0.f) return;

    // load q row (packed pairs)
    u64 q2[20];
    {
        int qb = (b == 0) ? 0 : 1;
        const ulonglong2* qp = (const ulonglong2*)(g_q + ((size_t)qb * HW + p) * CMODEL + head * DHEAD);
        #pragma unroll
        for (int d = 0; d < 10; ++d) {
            ulonglong2 qq = qp[d];
            q2[2 * d] = qq.x; q2[2 * d + 1] = qq.y;
        }
    }

    u64 acc2[20];
    #pragma unroll
    for (int d = 0; d < 20; ++d) acc2[d] = 0ULL;
    float l = 0.f;

    // single-pass softmax (no max subtraction: |scores| <~ 1.5, safe in fp32)
    #pragma unroll 1
    for (int j = 0; j < LSEQ; ++j) {
        const ulonglong2* kj = (const ulonglong2*)(ks + j * 20);
        u64 sA = 0ULL, sB = 0ULL;
        #pragma unroll
        for (int d = 0; d < 10; ++d) {
            ulonglong2 kk = kj[d];
            sA = ffma2(q2[2 * d], kk.x, sA);
            sB = ffma2(q2[2 * d + 1], kk.y, sB);
        }
        float2 fa = unpk2(sA), fb = unpk2(sB);
        float s = ((fa.x + fa.y) + (fb.x + fb.y)) * scale;
        float pe = __expf(s);
        l += pe;
        u64 pe2 = pack2(pe, pe);
        const ulonglong2* vj = (const ulonglong2*)(vs + j * 20);
        #pragma unroll
        for (int d = 0; d < 10; ++d) {
            ulonglong2 vv = vj[d];
            acc2[2 * d]     = ffma2(pe2, vv.x, acc2[2 * d]);
            acc2[2 * d + 1] = ffma2(pe2, vv.y, acc2[2 * d + 1]);
        }
    }

    float inv = 1.f / l;
    float sc = (b == 0) ? inv : wg * inv;   // pre-weighted; reduce kernel just sums
    #pragma unroll
    for (int d = 0; d < 10; ++d) {
        float2 x = unpk2(acc2[2 * d]);
        float2 y = unpk2(acc2[2 * d + 1]);
        o4[d] = make_float4(x.x * sc, x.y * sc, y.x * sc, y.y * sc);
    }
}

// ---------------- sum the 9 pre-weighted batch outputs (w-aware) -----------
__global__ void __launch_bounds__(256) reduce9_kernel()
{
    int idx = blockIdx.x * 256 + threadIdx.x;   // over HW*CMODEL/4 float4s
    int p = idx / (CMODEL / 4);                 // pixel of this float4
    const float4* o4 = (const float4*)g_O;
    const size_t stride = (size_t)HW * CMODEL / 4;
    float4 s = make_float4(0.f, 0.f, 0.f, 0.f);
    #pragma unroll
    for (int bb = 0; bb < NPHASE; ++bb) {
        if (g_w9[bb * HW + p] != 0.f) {         // skip exactly-zero rows (~85%)
            float4 v = o4[bb * stride + idx];
            s.x += v.x; s.y += v.y; s.z += v.z; s.w += v.w;
        }
    }
    ((float4*)(g_A + (size_t)HW * CMODEL))[idx] = s;
}

// ---------------- launch ---------------------------------------------------
extern "C" void kernel_launch(void* const* d_in, const int* in_sizes, int n_in,
                              void* d_out, int out_size)
{
    (void)in_sizes; (void)n_in; (void)out_size;
    const float* hs  = (const float*)d_in[0];
    const float* ehs = (const float*)d_in[1];
    const float* bb  = (const float*)d_in[2];
    const float* Wq  = (const float*)d_in[3];
    const float* Wk  = (const float*)d_in[4];
    const float* Wv  = (const float*)d_in[5];
    const float* Wo  = (const float*)d_in[6];
    const float* bo  = (const float*)d_in[7];
    float* out = (float*)d_out;

    weights_kernel<<<16, 256>>>(bb);

    dim3 gblk(8, 16);    // 128 threads, 8x8 micro
    qproj_kernel<<<dim3(CMODEL / 64, (2 * HW) / 128), gblk>>>(hs, Wq);
    kvproj_kernel<<<dim3(CMODEL / 64, (NB * LSEQ + 31) / 32), dim3(16, 16)>>>(ehs, Wk, Wv);

    att_kernel<<<dim3(HW / 128, HEADS, NB), 128>>>();

    reduce9_kernel<<<(HW * CMODEL / 4) / 256, 256>>>();

    outproj_kernel<<<dim3(CMODEL / 64, (2 * HW) / 128), gblk>>>(Wo, bo, out);
}

// round 13
// speedup vs baseline: 1.7044x; 1.0257x over previous
#include <cuda_runtime.h>
#include <math.h>

#define HEADS 8
#define DHEAD 40
#define CMODEL 320
#define CX 768
#define LSEQ 77
#define NB 10
#define HW 4096
#define NPHASE 9

typedef unsigned long long u64;

// ---------------- packed f32x2 helpers (FFMA2 path, sm_100+) ---------------
__device__ __forceinline__ u64 pack2(float lo, float hi) {
    u64 r; asm("mov.b64 %0, {%1, %2};" : "=l"(r) : "f"(lo), "f"(hi)); return r;
}
__device__ __forceinline__ float2 unpk2(u64 v) {
    float2 f; asm("mov.b64 {%0, %1}, %2;" : "=f"(f.x), "=f"(f.y) : "l"(v)); return f;
}
__device__ __forceinline__ u64 ffma2(u64 a, u64 b, u64 c) {
    u64 d; asm("fma.rn.f32x2 %0, %1, %2, %3;" : "=l"(d) : "l"(a), "l"(b), "l"(c)); return d;
}

// ---------------- scratch (device globals; no allocation allowed) ----------
__device__ __align__(16) float g_q[2 * HW * CMODEL];
__device__ __align__(16) float g_k[NB * LSEQ * CMODEL];
__device__ __align__(16) float g_v[NB * LSEQ * CMODEL];
__device__ __align__(16) float g_A[2 * HW * CMODEL];      // [0:HW)=uncond, [HW:2HW)=weighted sum
__device__ __align__(16) float g_O[NPHASE * HW * CMODEL]; // per-batch weighted outputs (b=1..9)
__device__ __align__(16) float g_w9[NPHASE * HW];
__device__ __align__(16) float g_wsum[HW];

// ---------------- phase weights (jax.image.resize bilinear+antialias) ------
__device__ __forceinline__ float resize_factor(int o, float lo, float hi) {
    float sf = (o + 0.5f) * 8.0f - 0.5f;
    float num = 0.f, den = 0.f;
    int h0 = o * 8 - 4, h1 = o * 8 + 11;
    #pragma unroll 1
    for (int h = h0; h <= h1; ++h) {
        if (h < 0 || h > 511) continue;
        float fh = (float)h;
        float wgt = 1.0f - fabsf(fh - sf) * 0.125f;
        den += wgt;
        if (fh >= lo && fh < hi) num += wgt;
    }
    return num / den;
}

__global__ void weights_kernel(const float* __restrict__ bboxes) {
    int p = blockIdx.x * blockDim.x + threadIdx.x;
    if (p >= HW) return;
    int r = p >> 6, c = p & 63;
    float s = 0.1f;
    g_w9[p] = 0.1f;
    #pragma unroll 1
    for (int i = 0; i < 8; ++i) {
        float x0 = bboxes[i * 4 + 0], y0 = bboxes[i * 4 + 1];
        float x1 = bboxes[i * 4 + 2], y1 = bboxes[i * 4 + 3];
        float wmin = floorf(512.f * x0), wmax = floorf(512.f * x1);
        float hmin = floorf(512.f * y0), hmax = floorf(512.f * y1);
        float wv = 10.f * resize_factor(r, hmin, hmax) * resize_factor(c, wmin, wmax);
        g_w9[(i + 1) * HW + p] = wv;
        s += wv;
    }
    g_wsum[p] = s;
}

// ---------------- fused K+V projection: 32x64 tile (125 blocks) ------------
__global__ void __launch_bounds__(256) kvproj_kernel(
    const float* __restrict__ ehs,
    const float* __restrict__ Wk, const float* __restrict__ Wv)
{
    __shared__ __align__(16) float As[16][36];
    __shared__ __align__(16) float Bk[16][64];
    __shared__ __align__(16) float Bv[16][64];
    const int tx = threadIdx.x, ty = threadIdx.y;
    const int t  = ty * 16 + tx;
    const int row0 = blockIdx.y * 32, col0 = blockIdx.x * 64;
    const int li = t >> 3, lk = (t & 7) << 1;    // A: 32 rows x 16 k, float2 each
    const int bk = t >> 4, bj = (t & 15) << 2;

    u64 ak[4], av[4];
    #pragma unroll
    for (int j = 0; j < 4; ++j) { ak[j] = 0ULL; av[j] = 0ULL; }

    for (int k0 = 0; k0 < CX; k0 += 16) {
        // rows up to 799 < 847 total in ehs — unguarded load is safe
        float2 a = *(const float2*)(ehs + (size_t)(row0 + li) * CX + k0 + lk);
        As[lk + 0][li] = a.x; As[lk + 1][li] = a.y;
        *(float4*)(&Bk[bk][bj]) = *(const float4*)(Wk + (size_t)(k0 + bk) * CMODEL + col0 + bj);
        *(float4*)(&Bv[bk][bj]) = *(const float4*)(Wv + (size_t)(k0 + bk) * CMODEL + col0 + bj);
        __syncthreads();
        #pragma unroll
        for (int kk = 0; kk < 16; ++kk) {
            u64 ap = *(const u64*)(&As[kk][ty * 2]);   // row pair (2ty, 2ty+1)
            float4 b1 = *(const float4*)(&Bk[kk][tx * 4]);
            float4 b2 = *(const float4*)(&Bv[kk][tx * 4]);
            ak[0] = ffma2(ap, pack2(b1.x, b1.x), ak[0]);
            ak[1] = ffma2(ap, pack2(b1.y, b1.y), ak[1]);
            ak[2] = ffma2(ap, pack2(b1.z, b1.z), ak[2]);
            ak[3] = ffma2(ap, pack2(b1.w, b1.w), ak[3]);
            av[0] = ffma2(ap, pack2(b2.x, b2.x), av[0]);
            av[1] = ffma2(ap, pack2(b2.y, b2.y), av[1]);
            av[2] = ffma2(ap, pack2(b2.z, b2.z), av[2]);
            av[3] = ffma2(ap, pack2(b2.w, b2.w), av[3]);
        }
        __syncthreads();
    }
    float2 c0 = unpk2(ak[0]), c1 = unpk2(ak[1]), c2 = unpk2(ak[2]), c3 = unpk2(ak[3]);
    float2 d0 = unpk2(av[0]), d1 = unpk2(av[1]), d2 = unpk2(av[2]), d3 = unpk2(av[3]);
    int re = row0 + ty * 2;
    if (re < NB * LSEQ) {
        *(float4*)(g_k + (size_t)re * CMODEL + col0 + tx * 4) = make_float4(c0.x, c1.x, c2.x, c3.x);
        *(float4*)(g_v + (size_t)re * CMODEL + col0 + tx * 4) = make_float4(d0.x, d1.x, d2.x, d3.x);
    }
    if (re + 1 < NB * LSEQ) {
        *(float4*)(g_k + (size_t)(re + 1) * CMODEL + col0 + tx * 4) = make_float4(c0.y, c1.y, c2.y, c3.y);
        *(float4*)(g_v + (size_t)(re + 1) * CMODEL + col0 + tx * 4) = make_float4(d0.y, d1.y, d2.y, d3.y);
    }
}

// ---------------- 128x64 GEMM core, 8x8 micro, block (8,16), pipelined -----
// Thread (tx,ty): rows ty*8..+7 (4 pairs), cols col0+{tx*4..+3, 32+tx*4..+3}.
// Next K-tile is prefetched into registers before the compute loop so the
// global-load latency overlaps the 16-step FFMA2 burst.
__device__ __forceinline__ void gemm128_f2(
    const float* __restrict__ A, const float* __restrict__ B,
    int K, int N, u64 (&acc)[4][8])
{
    __shared__ __align__(16) float As[16][132];
    __shared__ __align__(16) float Bs[16][64];
    const int tx = threadIdx.x, ty = threadIdx.y;   // tx 0..7, ty 0..15
    const int t  = ty * 8 + tx;                     // 0..127
    const int row0 = blockIdx.y * 128, col0 = blockIdx.x * 64;
    const int bk = t >> 3, bj = (t & 7) << 3;       // B: 16 k-rows x 64 cols, 8 floats/thr

    #pragma unroll
    for (int i = 0; i < 4; ++i)
        #pragma unroll
        for (int j = 0; j < 8; ++j) acc[i][j] = 0ULL;

    const float* apg = A + (size_t)(row0 + t) * K;
    const float* bpg = B + (size_t)bk * N + col0 + bj;

    float4 ar[4];
    float4 br[2];
    #pragma unroll
    for (int j = 0; j < 4; ++j) ar[j] = *(const float4*)(apg + 4 * j);
    br[0] = *(const float4*)(bpg);
    br[1] = *(const float4*)(bpg + 4);

    for (int k0 = 0; k0 < K; k0 += 16) {
        // store current tile regs -> smem
        #pragma unroll
        for (int j = 0; j < 4; ++j) {
            As[4 * j + 0][t] = ar[j].x; As[4 * j + 1][t] = ar[j].y;
            As[4 * j + 2][t] = ar[j].z; As[4 * j + 3][t] = ar[j].w;
        }
        *(float4*)(&Bs[bk][bj])     = br[0];
        *(float4*)(&Bs[bk][bj + 4]) = br[1];
        __syncthreads();

        // prefetch next tile (overlaps with compute below)
        if (k0 + 16 < K) {
            #pragma unroll
            for (int j = 0; j < 4; ++j) ar[j] = *(const float4*)(apg + k0 + 16 + 4 * j);
            br[0] = *(const float4*)(bpg + (size_t)(k0 + 16) * N);
            br[1] = *(const float4*)(bpg + (size_t)(k0 + 16) * N + 4);
        }

        #pragma unroll
        for (int kk = 0; kk < 16; ++kk) {
            const ulonglong2* arow = (const ulonglong2*)(&As[kk][ty * 8]);
            ulonglong2 aA = arow[0], aB = arow[1];   // row pairs (0,1),(2,3),(4,5),(6,7)
            float4 blo = *(const float4*)(&Bs[kk][tx * 4]);
            float4 bhi = *(const float4*)(&Bs[kk][32 + tx * 4]);
            u64 s0 = pack2(blo.x, blo.x), s1 = pack2(blo.y, blo.y);
            u64 s2 = pack2(blo.z, blo.z), s3 = pack2(blo.w, blo.w);
            u64 s4 = pack2(bhi.x, bhi.x), s5 = pack2(bhi.y, bhi.y);
            u64 s6 = pack2(bhi.z, bhi.z), s7 = pack2(bhi.w, bhi.w);
            acc[0][0] = ffma2(aA.x, s0, acc[0][0]); acc[0][1] = ffma2(aA.x, s1, acc[0][1]);
            acc[0][2] = ffma2(aA.x, s2, acc[0][2]); acc[0][3] = ffma2(aA.x, s3, acc[0][3]);
            acc[0][4] = ffma2(aA.x, s4, acc[0][4]); acc[0][5] = ffma2(aA.x, s5, acc[0][5]);
            acc[0][6] = ffma2(aA.x, s6, acc[0][6]); acc[0][7] = ffma2(aA.x, s7, acc[0][7]);
            acc[1][0] = ffma2(aA.y, s0, acc[1][0]); acc[1][1] = ffma2(aA.y, s1, acc[1][1]);
            acc[1][2] = ffma2(aA.y, s2, acc[1][2]); acc[1][3] = ffma2(aA.y, s3, acc[1][3]);
            acc[1][4] = ffma2(aA.y, s4, acc[1][4]); acc[1][5] = ffma2(aA.y, s5, acc[1][5]);
            acc[1][6] = ffma2(aA.y, s6, acc[1][6]); acc[1][7] = ffma2(aA.y, s7, acc[1][7]);
            acc[2][0] = ffma2(aB.x, s0, acc[2][0]); acc[2][1] = ffma2(aB.x, s1, acc[2][1]);
            acc[2][2] = ffma2(aB.x, s2, acc[2][2]); acc[2][3] = ffma2(aB.x, s3, acc[2][3]);
            acc[2][4] = ffma2(aB.x, s4, acc[2][4]); acc[2][5] = ffma2(aB.x, s5, acc[2][5]);
            acc[2][6] = ffma2(aB.x, s6, acc[2][6]); acc[2][7] = ffma2(aB.x, s7, acc[2][7]);
            acc[3][0] = ffma2(aB.y, s0, acc[3][0]); acc[3][1] = ffma2(aB.y, s1, acc[3][1]);
            acc[3][2] = ffma2(aB.y, s2, acc[3][2]); acc[3][3] = ffma2(aB.y, s3, acc[3][3]);
            acc[3][4] = ffma2(aB.y, s4, acc[3][4]); acc[3][5] = ffma2(aB.y, s5, acc[3][5]);
            acc[3][6] = ffma2(aB.y, s6, acc[3][6]); acc[3][7] = ffma2(aB.y, s7, acc[3][7]);
        }
        __syncthreads();
    }
}

// Q projection: [8192,320] x [320,320] -> g_q
__global__ void __launch_bounds__(128) qproj_kernel(
    const float* __restrict__ hs, const float* __restrict__ Wq)
{
    u64 acc[4][8];
    gemm128_f2(hs, Wq, CMODEL, CMODEL, acc);
    const int row0 = blockIdx.y * 128, col0 = blockIdx.x * 64;
    const int tx = threadIdx.x, ty = threadIdx.y;
    #pragma unroll
    for (int i = 0; i < 4; ++i) {
        float2 p[8];
        #pragma unroll
        for (int j = 0; j < 8; ++j) p[j] = unpk2(acc[i][j]);
        int re = row0 + ty * 8 + 2 * i;
        float* r0 = g_q + (size_t)re * CMODEL + col0;
        float* r1 = r0 + CMODEL;
        *(float4*)(r0 + tx * 4)      = make_float4(p[0].x, p[1].x, p[2].x, p[3].x);
        *(float4*)(r0 + 32 + tx * 4) = make_float4(p[4].x, p[5].x, p[6].x, p[7].x);
        *(float4*)(r1 + tx * 4)      = make_float4(p[0].y, p[1].y, p[2].y, p[3].y);
        *(float4*)(r1 + 32 + tx * 4) = make_float4(p[4].y, p[5].y, p[6].y, p[7].y);
    }
}

// Output projection + fused epilogue
__global__ void __launch_bounds__(128) outproj_kernel(
    const float* __restrict__ Wo, const float* __restrict__ bo,
    float* __restrict__ out)
{
    u64 acc[4][8];
    gemm128_f2(g_A, Wo, CMODEL, CMODEL, acc);
    const int row0 = blockIdx.y * 128, col0 = blockIdx.x * 64;
    const int tx = threadIdx.x, ty = threadIdx.y;
    const int cA = col0 + tx * 4, cB = col0 + 32 + tx * 4;
    float4 bA = *(const float4*)(bo + cA);
    float4 bB = *(const float4*)(bo + cB);
    #pragma unroll
    for (int i = 0; i < 4; ++i) {
        float2 p[8];
        #pragma unroll
        for (int j = 0; j < 8; ++j) p[j] = unpk2(acc[i][j]);
        #pragma unroll
        for (int h = 0; h < 2; ++h) {
            int r = row0 + ty * 8 + 2 * i + h;
            float v0 = h ? p[0].y : p[0].x, v1 = h ? p[1].y : p[1].x;
            float v2 = h ? p[2].y : p[2].x, v3 = h ? p[3].y : p[3].x;
            float v4 = h ? p[4].y : p[4].x, v5 = h ? p[5].y : p[5].x;
            float v6 = h ? p[6].y : p[6].x, v7 = h ? p[7].y : p[7].x;
            float4 oA, oB;
            if (r < HW) {
                oA = make_float4(v0 + bA.x, v1 + bA.y, v2 + bA.z, v3 + bA.w);
                oB = make_float4(v4 + bB.x, v5 + bB.y, v6 + bB.z, v7 + bB.w);
            } else {
                float ws = g_wsum[r - HW];
                float invD = 1.f / (ws + 1e-6f);
                float bs = ws * invD;
                oA = make_float4(v0 * invD + bA.x * bs, v1 * invD + bA.y * bs,
                                 v2 * invD + bA.z * bs, v3 * invD + bA.w * bs);
                oB = make_float4(v4 * invD + bB.x * bs, v5 * invD + bB.y * bs,
                                 v6 * invD + bB.z * bs, v7 * invD + bB.w * bs);
            }
            *(float4*)(out + (size_t)r * CMODEL + cA) = oA;
            *(float4*)(out + (size_t)r * CMODEL + cB) = oB;
        }
    }
}

// ---------------- attention: thread-pair per pixel (256 thr / 128 px) ------
// Each pair lane owns 20 of the 40 head dims; score combined via shfl_xor.
// Zero-weight (batch,pixel) rows are skipped entirely (reduce9 never reads
// them). Skip decisions are pair-uniform, so the shuffle partner is always
// alive; __activemask() after the skips is converged.
__global__ void __launch_bounds__(256) att_kernel()
{
    __shared__ __align__(16) u64 ks[LSEQ * 20];   // 77 rows x 40 floats (20 u64)
    __shared__ __align__(16) u64 vs[LSEQ * 20];
    const int head = blockIdx.y;
    const int b = blockIdx.z;
    const int t = threadIdx.x;        // 0..255
    const int pl = t >> 1;            // local pixel 0..127
    const int half = t & 1;           // dim half: floats [half*20, half*20+20)
    const int p = blockIdx.x * 128 + pl;
    const float scale = 0.15811388300841897f;     // 1/sqrt(40)

    float wg = 1.f;
    float* optr;
    if (b == 0) {
        optr = g_A + (size_t)p * CMODEL + head * DHEAD;
    } else {
        wg = g_w9[(b - 1) * HW + p];
        optr = g_O + ((size_t)(b - 1) * HW + p) * CMODEL + head * DHEAD;
    }
    float4* o4 = (float4*)(optr + half * 20);

    // whole-block skip (bbox rectangles cover ~15% of pixels for b>=2)
    int any = __syncthreads_count(wg != 0.f);
    if (any == 0) return;

    // stage K/V head tile (16B vectors; CMODEL row = 80 ulonglong2)
    {
        const ulonglong2* gk = (const ulonglong2*)g_k;
        const ulonglong2* gv = (const ulonglong2*)g_v;
        ulonglong2* ks2 = (ulonglong2*)ks;
        ulonglong2* vs2 = (ulonglong2*)vs;
        for (int idx = t; idx < LSEQ * 10; idx += 256) {
            int j = idx / 10, d = idx - j * 10;
            int g = (b * LSEQ + j) * 80 + head * 10 + d;
            ks2[idx] = gk[g];
            vs2[idx] = gv[g];
        }
    }
    __syncthreads();

    // per-thread skip (pair-uniform); no further barriers below
    if (wg == 0.f) return;
    unsigned umask = __activemask();

    // load this half's 20 q floats (5 ulonglong2)
    u64 q2[10];
    {
        int qb = (b == 0) ? 0 : 1;
        const ulonglong2* qp = (const ulonglong2*)(
            g_q + ((size_t)qb * HW + p) * CMODEL + head * DHEAD + half * 20);
        #pragma unroll
        for (int d = 0; d < 5; ++d) {
            ulonglong2 qq = qp[d];
            q2[2 * d] = qq.x; q2[2 * d + 1] = qq.y;
        }
    }

    u64 acc2[10];
    #pragma unroll
    for (int d = 0; d < 10; ++d) acc2[d] = 0ULL;
    float l = 0.f;

    // single-pass softmax (no max subtraction: |scores| <~ 1.5, safe in fp32)
    #pragma unroll 1
    for (int j = 0; j < LSEQ; ++j) {
        const ulonglong2* kj = (const ulonglong2*)(ks + j * 20 + half * 10);
        u64 sA = 0ULL, sB = 0ULL;
        #pragma unroll
        for (int d = 0; d < 5; ++d) {
            ulonglong2 kk = kj[d];
            sA = ffma2(q2[2 * d], kk.x, sA);
            sB = ffma2(q2[2 * d + 1], kk.y, sB);
        }
        float2 fa = unpk2(sA), fb = unpk2(sB);
        float part = (fa.x + fa.y) + (fb.x + fb.y);
        part += __shfl_xor_sync(umask, part, 1);   // combine the two halves
        float pe = __expf(part * scale);
        l += pe;
        u64 pe2 = pack2(pe, pe);
        const ulonglong2* vj = (const ulonglong2*)(vs + j * 20 + half * 10);
        #pragma unroll
        for (int d = 0; d < 5; ++d) {
            ulonglong2 vv = vj[d];
            acc2[2 * d]     = ffma2(pe2, vv.x, acc2[2 * d]);
            acc2[2 * d + 1] = ffma2(pe2, vv.y, acc2[2 * d + 1]);
        }
    }

    float inv = 1.f / l;
    float sc = (b == 0) ? inv : wg * inv;   // pre-weighted; reduce kernel just sums
    #pragma unroll
    for (int d = 0; d < 5; ++d) {
        float2 x = unpk2(acc2[2 * d]);
        float2 y = unpk2(acc2[2 * d + 1]);
        o4[d] = make_float4(x.x * sc, x.y * sc, y.x * sc, y.y * sc);
    }
}

// ---------------- sum the 9 pre-weighted batch outputs (w-aware) -----------
__global__ void __launch_bounds__(256) reduce9_kernel()
{
    int idx = blockIdx.x * 256 + threadIdx.x;   // over HW*CMODEL/4 float4s
    int p = idx / (CMODEL / 4);                 // pixel of this float4
    const float4* o4 = (const float4*)g_O;
    const size_t stride = (size_t)HW * CMODEL / 4;
    float4 s = make_float4(0.f, 0.f, 0.f, 0.f);
    #pragma unroll
    for (int bb = 0; bb < NPHASE; ++bb) {
        if (g_w9[bb * HW + p] != 0.f) {         // skip exactly-zero rows (~85%)
            float4 v = o4[bb * stride + idx];
            s.x += v.x; s.y += v.y; s.z += v.z; s.w += v.w;
        }
    }
    ((float4*)(g_A + (size_t)HW * CMODEL))[idx] = s;
}

// ---------------- launch ---------------------------------------------------
extern "C" void kernel_launch(void* const* d_in, const int* in_sizes, int n_in,
                              void* d_out, int out_size)
{
    (void)in_sizes; (void)n_in; (void)out_size;
    const float* hs  = (const float*)d_in[0];
    const float* ehs = (const float*)d_in[1];
    const float* bb  = (const float*)d_in[2];
    const float* Wq  = (const float*)d_in[3];
    const float* Wk  = (const float*)d_in[4];
    const float* Wv  = (const float*)d_in[5];
    const float* Wo  = (const float*)d_in[6];
    const float* bo  = (const float*)d_in[7];
    float* out = (float*)d_out;

    weights_kernel<<<16, 256>>>(bb);

    dim3 gblk(8, 16);    // 128 threads, 8x8 micro
    qproj_kernel<<<dim3(CMODEL / 64, (2 * HW) / 128), gblk>>>(hs, Wq);
    kvproj_kernel<<<dim3(CMODEL / 64, (NB * LSEQ + 31) / 32), dim3(16, 16)>>>(ehs, Wk, Wv);

    att_kernel<<<dim3(HW / 128, HEADS, NB), 256>>>();

    reduce9_kernel<<<(HW * CMODEL / 4) / 256, 256>>>();

    outproj_kernel<<<dim3(CMODEL / 64, (2 * HW) / 128), gblk>>>(Wo, bo, out);
}

// round 14
// speedup vs baseline: 1.7575x; 1.0311x over previous
#include <cuda_runtime.h>
#include <math.h>

#define HEADS 8
#define DHEAD 40
#define CMODEL 320
#define CX 768
#define LSEQ 77
#define NB 10
#define HW 4096
#define NPHASE 9

typedef unsigned long long u64;

// ---------------- packed f32x2 helpers (FFMA2 path, sm_100+) ---------------
__device__ __forceinline__ u64 pack2(float lo, float hi) {
    u64 r; asm("mov.b64 %0, {%1, %2};" : "=l"(r) : "f"(lo), "f"(hi)); return r;
}
__device__ __forceinline__ float2 unpk2(u64 v) {
    float2 f; asm("mov.b64 {%0, %1}, %2;" : "=f"(f.x), "=f"(f.y) : "l"(v)); return f;
}
__device__ __forceinline__ u64 ffma2(u64 a, u64 b, u64 c) {
    u64 d; asm("fma.rn.f32x2 %0, %1, %2, %3;" : "=l"(d) : "l"(a), "l"(b), "l"(c)); return d;
}

// ---------------- scratch (device globals; no allocation allowed) ----------
__device__ __align__(16) float g_q[2 * HW * CMODEL];
__device__ __align__(16) float g_k[NB * LSEQ * CMODEL];
__device__ __align__(16) float g_v[NB * LSEQ * CMODEL];
__device__ __align__(16) float g_A[2 * HW * CMODEL];      // [0:HW)=uncond, [HW:2HW)=weighted sum
__device__ __align__(16) float g_O[NPHASE * HW * CMODEL]; // per-batch weighted outputs (b=1..9)
__device__ __align__(16) float g_w9[NPHASE * HW];
__device__ __align__(16) float g_wsum[HW];

// ---------------- phase weights (jax.image.resize bilinear+antialias) ------
__device__ __forceinline__ float resize_factor(int o, float lo, float hi) {
    float sf = (o + 0.5f) * 8.0f - 0.5f;
    float num = 0.f, den = 0.f;
    int h0 = o * 8 - 4, h1 = o * 8 + 11;
    #pragma unroll 1
    for (int h = h0; h <= h1; ++h) {
        if (h < 0 || h > 511) continue;
        float fh = (float)h;
        float wgt = 1.0f - fabsf(fh - sf) * 0.125f;
        den += wgt;
        if (fh >= lo && fh < hi) num += wgt;
    }
    return num / den;
}

__global__ void weights_kernel(const float* __restrict__ bboxes) {
    int p = blockIdx.x * blockDim.x + threadIdx.x;
    if (p >= HW) return;
    int r = p >> 6, c = p & 63;
    float s = 0.1f;
    g_w9[p] = 0.1f;
    #pragma unroll 1
    for (int i = 0; i < 8; ++i) {
        float x0 = bboxes[i * 4 + 0], y0 = bboxes[i * 4 + 1];
        float x1 = bboxes[i * 4 + 2], y1 = bboxes[i * 4 + 3];
        float wmin = floorf(512.f * x0), wmax = floorf(512.f * x1);
        float hmin = floorf(512.f * y0), hmax = floorf(512.f * y1);
        float wv = 10.f * resize_factor(r, hmin, hmax) * resize_factor(c, wmin, wmax);
        g_w9[(i + 1) * HW + p] = wv;
        s += wv;
    }
    g_wsum[p] = s;
}

// ---------------- fused K+V projection: 32x64 tile (125 blocks) ------------
__global__ void __launch_bounds__(256) kvproj_kernel(
    const float* __restrict__ ehs,
    const float* __restrict__ Wk, const float* __restrict__ Wv)
{
    __shared__ __align__(16) float As[16][36];
    __shared__ __align__(16) float Bk[16][64];
    __shared__ __align__(16) float Bv[16][64];
    const int tx = threadIdx.x, ty = threadIdx.y;
    const int t  = ty * 16 + tx;
    const int row0 = blockIdx.y * 32, col0 = blockIdx.x * 64;
    const int li = t >> 3, lk = (t & 7) << 1;    // A: 32 rows x 16 k, float2 each
    const int bk = t >> 4, bj = (t & 15) << 2;

    u64 ak[4], av[4];
    #pragma unroll
    for (int j = 0; j < 4; ++j) { ak[j] = 0ULL; av[j] = 0ULL; }

    for (int k0 = 0; k0 < CX; k0 += 16) {
        // rows up to 799 < 847 total in ehs — unguarded load is safe
        float2 a = *(const float2*)(ehs + (size_t)(row0 + li) * CX + k0 + lk);
        As[lk + 0][li] = a.x; As[lk + 1][li] = a.y;
        *(float4*)(&Bk[bk][bj]) = *(const float4*)(Wk + (size_t)(k0 + bk) * CMODEL + col0 + bj);
        *(float4*)(&Bv[bk][bj]) = *(const float4*)(Wv + (size_t)(k0 + bk) * CMODEL + col0 + bj);
        __syncthreads();
        #pragma unroll
        for (int kk = 0; kk < 16; ++kk) {
            u64 ap = *(const u64*)(&As[kk][ty * 2]);   // row pair (2ty, 2ty+1)
            float4 b1 = *(const float4*)(&Bk[kk][tx * 4]);
            float4 b2 = *(const float4*)(&Bv[kk][tx * 4]);
            ak[0] = ffma2(ap, pack2(b1.x, b1.x), ak[0]);
            ak[1] = ffma2(ap, pack2(b1.y, b1.y), ak[1]);
            ak[2] = ffma2(ap, pack2(b1.z, b1.z), ak[2]);
            ak[3] = ffma2(ap, pack2(b1.w, b1.w), ak[3]);
            av[0] = ffma2(ap, pack2(b2.x, b2.x), av[0]);
            av[1] = ffma2(ap, pack2(b2.y, b2.y), av[1]);
            av[2] = ffma2(ap, pack2(b2.z, b2.z), av[2]);
            av[3] = ffma2(ap, pack2(b2.w, b2.w), av[3]);
        }
        __syncthreads();
    }
    float2 c0 = unpk2(ak[0]), c1 = unpk2(ak[1]), c2 = unpk2(ak[2]), c3 = unpk2(ak[3]);
    float2 d0 = unpk2(av[0]), d1 = unpk2(av[1]), d2 = unpk2(av[2]), d3 = unpk2(av[3]);
    int re = row0 + ty * 2;
    if (re < NB * LSEQ) {
        *(float4*)(g_k + (size_t)re * CMODEL + col0 + tx * 4) = make_float4(c0.x, c1.x, c2.x, c3.x);
        *(float4*)(g_v + (size_t)re * CMODEL + col0 + tx * 4) = make_float4(d0.x, d1.x, d2.x, d3.x);
    }
    if (re + 1 < NB * LSEQ) {
        *(float4*)(g_k + (size_t)(re + 1) * CMODEL + col0 + tx * 4) = make_float4(c0.y, c1.y, c2.y, c3.y);
        *(float4*)(g_v + (size_t)(re + 1) * CMODEL + col0 + tx * 4) = make_float4(d0.y, d1.y, d2.y, d3.y);
    }
}

// ---------------- 128x64 GEMM core, 8x8 micro, double-buffered smem --------
// Thread (tx,ty): rows ty*8..+7 (4 pairs), cols col0+{tx*4..+3, 32+tx*4..+3}.
// ONE barrier per K-tile: prefetched tile goes to the other smem buffer
// (last read before the previous barrier), compute overlaps global loads.
__device__ __forceinline__ void gemm128_f2(
    const float* __restrict__ A, const float* __restrict__ B,
    int K, int N, u64 (&acc)[4][8])
{
    __shared__ __align__(16) float As[2][16][132];
    __shared__ __align__(16) float Bs[2][16][64];
    const int tx = threadIdx.x, ty = threadIdx.y;   // tx 0..7, ty 0..15
    const int t  = ty * 8 + tx;                     // 0..127
    const int row0 = blockIdx.y * 128, col0 = blockIdx.x * 64;
    const int bk = t >> 3, bj = (t & 7) << 3;       // B: 16 k-rows x 64 cols, 8 floats/thr

    #pragma unroll
    for (int i = 0; i < 4; ++i)
        #pragma unroll
        for (int j = 0; j < 8; ++j) acc[i][j] = 0ULL;

    const float* apg = A + (size_t)(row0 + t) * K;
    const float* bpg = B + (size_t)bk * N + col0 + bj;

    // stage tile 0 into buffer 0
    {
        #pragma unroll
        for (int j = 0; j < 4; ++j) {
            float4 a = *(const float4*)(apg + 4 * j);
            As[0][4 * j + 0][t] = a.x; As[0][4 * j + 1][t] = a.y;
            As[0][4 * j + 2][t] = a.z; As[0][4 * j + 3][t] = a.w;
        }
        *(float4*)(&Bs[0][bk][bj])     = *(const float4*)(bpg);
        *(float4*)(&Bs[0][bk][bj + 4]) = *(const float4*)(bpg + 4);
    }
    __syncthreads();

    int cur = 0;
    for (int k0 = 0; k0 < K; k0 += 16) {
        // prefetch next tile into regs (overlaps the compute below)
        float4 ar[4]; float4 br0, br1;
        const bool more = (k0 + 16 < K);
        if (more) {
            #pragma unroll
            for (int j = 0; j < 4; ++j) ar[j] = *(const float4*)(apg + k0 + 16 + 4 * j);
            br0 = *(const float4*)(bpg + (size_t)(k0 + 16) * N);
            br1 = *(const float4*)(bpg + (size_t)(k0 + 16) * N + 4);
        }

        #pragma unroll
        for (int kk = 0; kk < 16; ++kk) {
            const ulonglong2* arow = (const ulonglong2*)(&As[cur][kk][ty * 8]);
            ulonglong2 aA = arow[0], aB = arow[1];   // row pairs (0,1),(2,3),(4,5),(6,7)
            float4 blo = *(const float4*)(&Bs[cur][kk][tx * 4]);
            float4 bhi = *(const float4*)(&Bs[cur][kk][32 + tx * 4]);
            u64 s0 = pack2(blo.x, blo.x), s1 = pack2(blo.y, blo.y);
            u64 s2 = pack2(blo.z, blo.z), s3 = pack2(blo.w, blo.w);
            u64 s4 = pack2(bhi.x, bhi.x), s5 = pack2(bhi.y, bhi.y);
            u64 s6 = pack2(bhi.z, bhi.z), s7 = pack2(bhi.w, bhi.w);
            acc[0][0] = ffma2(aA.x, s0, acc[0][0]); acc[0][1] = ffma2(aA.x, s1, acc[0][1]);
            acc[0][2] = ffma2(aA.x, s2, acc[0][2]); acc[0][3] = ffma2(aA.x, s3, acc[0][3]);
            acc[0][4] = ffma2(aA.x, s4, acc[0][4]); acc[0][5] = ffma2(aA.x, s5, acc[0][5]);
            acc[0][6] = ffma2(aA.x, s6, acc[0][6]); acc[0][7] = ffma2(aA.x, s7, acc[0][7]);
            acc[1][0] = ffma2(aA.y, s0, acc[1][0]); acc[1][1] = ffma2(aA.y, s1, acc[1][1]);
            acc[1][2] = ffma2(aA.y, s2, acc[1][2]); acc[1][3] = ffma2(aA.y, s3, acc[1][3]);
            acc[1][4] = ffma2(aA.y, s4, acc[1][4]); acc[1][5] = ffma2(aA.y, s5, acc[1][5]);
            acc[1][6] = ffma2(aA.y, s6, acc[1][6]); acc[1][7] = ffma2(aA.y, s7, acc[1][7]);
            acc[2][0] = ffma2(aB.x, s0, acc[2][0]); acc[2][1] = ffma2(aB.x, s1, acc[2][1]);
            acc[2][2] = ffma2(aB.x, s2, acc[2][2]); acc[2][3] = ffma2(aB.x, s3, acc[2][3]);
            acc[2][4] = ffma2(aB.x, s4, acc[2][4]); acc[2][5] = ffma2(aB.x, s5, acc[2][5]);
            acc[2][6] = ffma2(aB.x, s6, acc[2][6]); acc[2][7] = ffma2(aB.x, s7, acc[2][7]);
            acc[3][0] = ffma2(aB.y, s0, acc[3][0]); acc[3][1] = ffma2(aB.y, s1, acc[3][1]);
            acc[3][2] = ffma2(aB.y, s2, acc[3][2]); acc[3][3] = ffma2(aB.y, s3, acc[3][3]);
            acc[3][4] = ffma2(aB.y, s4, acc[3][4]); acc[3][5] = ffma2(aB.y, s5, acc[3][5]);
            acc[3][6] = ffma2(aB.y, s6, acc[3][6]); acc[3][7] = ffma2(aB.y, s7, acc[3][7]);
        }

        if (more) {
            // write into the other buffer — last read before the previous
            // barrier, so no race with this iteration's readers
            int nxt = cur ^ 1;
            #pragma unroll
            for (int j = 0; j < 4; ++j) {
                As[nxt][4 * j + 0][t] = ar[j].x; As[nxt][4 * j + 1][t] = ar[j].y;
                As[nxt][4 * j + 2][t] = ar[j].z; As[nxt][4 * j + 3][t] = ar[j].w;
            }
            *(float4*)(&Bs[nxt][bk][bj])     = br0;
            *(float4*)(&Bs[nxt][bk][bj + 4]) = br1;
            __syncthreads();
            cur = nxt;
        }
    }
}

// Q projection: [8192,320] x [320,320] -> g_q
__global__ void __launch_bounds__(128) qproj_kernel(
    const float* __restrict__ hs, const float* __restrict__ Wq)
{
    u64 acc[4][8];
    gemm128_f2(hs, Wq, CMODEL, CMODEL, acc);
    const int row0 = blockIdx.y * 128, col0 = blockIdx.x * 64;
    const int tx = threadIdx.x, ty = threadIdx.y;
    #pragma unroll
    for (int i = 0; i < 4; ++i) {
        float2 p[8];
        #pragma unroll
        for (int j = 0; j < 8; ++j) p[j] = unpk2(acc[i][j]);
        int re = row0 + ty * 8 + 2 * i;
        float* r0 = g_q + (size_t)re * CMODEL + col0;
        float* r1 = r0 + CMODEL;
        *(float4*)(r0 + tx * 4)      = make_float4(p[0].x, p[1].x, p[2].x, p[3].x);
        *(float4*)(r0 + 32 + tx * 4) = make_float4(p[4].x, p[5].x, p[6].x, p[7].x);
        *(float4*)(r1 + tx * 4)      = make_float4(p[0].y, p[1].y, p[2].y, p[3].y);
        *(float4*)(r1 + 32 + tx * 4) = make_float4(p[4].y, p[5].y, p[6].y, p[7].y);
    }
}

// Output projection + fused epilogue
__global__ void __launch_bounds__(128) outproj_kernel(
    const float* __restrict__ Wo, const float* __restrict__ bo,
    float* __restrict__ out)
{
    u64 acc[4][8];
    gemm128_f2(g_A, Wo, CMODEL, CMODEL, acc);
    const int row0 = blockIdx.y * 128, col0 = blockIdx.x * 64;
    const int tx = threadIdx.x, ty = threadIdx.y;
    const int cA = col0 + tx * 4, cB = col0 + 32 + tx * 4;
    float4 bA = *(const float4*)(bo + cA);
    float4 bB = *(const float4*)(bo + cB);
    #pragma unroll
    for (int i = 0; i < 4; ++i) {
        float2 p[8];
        #pragma unroll
        for (int j = 0; j < 8; ++j) p[j] = unpk2(acc[i][j]);
        #pragma unroll
        for (int h = 0; h < 2; ++h) {
            int r = row0 + ty * 8 + 2 * i + h;
            float v0 = h ? p[0].y : p[0].x, v1 = h ? p[1].y : p[1].x;
            float v2 = h ? p[2].y : p[2].x, v3 = h ? p[3].y : p[3].x;
            float v4 = h ? p[4].y : p[4].x, v5 = h ? p[5].y : p[5].x;
            float v6 = h ? p[6].y : p[6].x, v7 = h ? p[7].y : p[7].x;
            float4 oA, oB;
            if (r < HW) {
                oA = make_float4(v0 + bA.x, v1 + bA.y, v2 + bA.z, v3 + bA.w);
                oB = make_float4(v4 + bB.x, v5 + bB.y, v6 + bB.z, v7 + bB.w);
            } else {
                float ws = g_wsum[r - HW];
                float invD = 1.f / (ws + 1e-6f);
                float bs = ws * invD;
                oA = make_float4(v0 * invD + bA.x * bs, v1 * invD + bA.y * bs,
                                 v2 * invD + bA.z * bs, v3 * invD + bA.w * bs);
                oB = make_float4(v4 * invD + bB.x * bs, v5 * invD + bB.y * bs,
                                 v6 * invD + bB.z * bs, v7 * invD + bB.w * bs);
            }
            *(float4*)(out + (size_t)r * CMODEL + cA) = oA;
            *(float4*)(out + (size_t)r * CMODEL + cB) = oB;
        }
    }
}

// ---------------- attention: thread-pair per pixel, 2-key unroll -----------
// Each pair lane owns 20 of the 40 head dims; scores combined via shfl_xor.
// Two independent key chains per iteration hide SHFL+MUFU latency.
__global__ void __launch_bounds__(256) att_kernel()
{
    __shared__ __align__(16) u64 ks[LSEQ * 20];   // 77 rows x 40 floats (20 u64)
    __shared__ __align__(16) u64 vs[LSEQ * 20];
    const int head = blockIdx.y;
    const int b = blockIdx.z;
    const int t = threadIdx.x;        // 0..255
    const int pl = t >> 1;            // local pixel 0..127
    const int half = t & 1;           // dim half: floats [half*20, half*20+20)
    const int p = blockIdx.x * 128 + pl;
    const float scale = 0.15811388300841897f;     // 1/sqrt(40)

    float wg = 1.f;
    float* optr;
    if (b == 0) {
        optr = g_A + (size_t)p * CMODEL + head * DHEAD;
    } else {
        wg = g_w9[(b - 1) * HW + p];
        optr = g_O + ((size_t)(b - 1) * HW + p) * CMODEL + head * DHEAD;
    }
    float4* o4 = (float4*)(optr + half * 20);

    // whole-block skip (bbox rectangles cover ~15% of pixels for b>=2)
    int any = __syncthreads_count(wg != 0.f);
    if (any == 0) return;

    // stage K/V head tile (16B vectors; CMODEL row = 80 ulonglong2)
    {
        const ulonglong2* gk = (const ulonglong2*)g_k;
        const ulonglong2* gv = (const ulonglong2*)g_v;
        ulonglong2* ks2 = (ulonglong2*)ks;
        ulonglong2* vs2 = (ulonglong2*)vs;
        for (int idx = t; idx < LSEQ * 10; idx += 256) {
            int j = idx / 10, d = idx - j * 10;
            int g = (b * LSEQ + j) * 80 + head * 10 + d;
            ks2[idx] = gk[g];
            vs2[idx] = gv[g];
        }
    }
    __syncthreads();

    // per-thread skip (pair-uniform); no further barriers below
    if (wg == 0.f) return;
    unsigned umask = __activemask();

    // load this half's 20 q floats (5 ulonglong2)
    u64 q2[10];
    {
        int qb = (b == 0) ? 0 : 1;
        const ulonglong2* qp = (const ulonglong2*)(
            g_q + ((size_t)qb * HW + p) * CMODEL + head * DHEAD + half * 20);
        #pragma unroll
        for (int d = 0; d < 5; ++d) {
            ulonglong2 qq = qp[d];
            q2[2 * d] = qq.x; q2[2 * d + 1] = qq.y;
        }
    }

    u64 acc2[10];
    #pragma unroll
    for (int d = 0; d < 10; ++d) acc2[d] = 0ULL;
    float l = 0.f;

    // single-pass softmax, 2 keys per iteration (76 = 38*2, tail key 76)
    #pragma unroll 1
    for (int j = 0; j < LSEQ - 1; j += 2) {
        const ulonglong2* kj0 = (const ulonglong2*)(ks + j * 20 + half * 10);
        const ulonglong2* kj1 = (const ulonglong2*)(ks + (j + 1) * 20 + half * 10);
        u64 sA0 = 0ULL, sB0 = 0ULL, sA1 = 0ULL, sB1 = 0ULL;
        #pragma unroll
        for (int d = 0; d < 5; ++d) {
            ulonglong2 k0v = kj0[d], k1v = kj1[d];
            sA0 = ffma2(q2[2 * d], k0v.x, sA0); sB0 = ffma2(q2[2 * d + 1], k0v.y, sB0);
            sA1 = ffma2(q2[2 * d], k1v.x, sA1); sB1 = ffma2(q2[2 * d + 1], k1v.y, sB1);
        }
        float2 fa0 = unpk2(sA0), fb0 = unpk2(sB0);
        float2 fa1 = unpk2(sA1), fb1 = unpk2(sB1);
        float part0 = (fa0.x + fa0.y) + (fb0.x + fb0.y);
        float part1 = (fa1.x + fa1.y) + (fb1.x + fb1.y);
        part0 += __shfl_xor_sync(umask, part0, 1);
        part1 += __shfl_xor_sync(umask, part1, 1);
        float pe0 = __expf(part0 * scale);
        float pe1 = __expf(part1 * scale);
        l += pe0 + pe1;
        u64 pe20 = pack2(pe0, pe0), pe21 = pack2(pe1, pe1);
        const ulonglong2* vj0 = (const ulonglong2*)(vs + j * 20 + half * 10);
        const ulonglong2* vj1 = (const ulonglong2*)(vs + (j + 1) * 20 + half * 10);
        #pragma unroll
        for (int d = 0; d < 5; ++d) {
            ulonglong2 v0 = vj0[d], v1 = vj1[d];
            acc2[2 * d]     = ffma2(pe20, v0.x, acc2[2 * d]);
            acc2[2 * d + 1] = ffma2(pe20, v0.y, acc2[2 * d + 1]);
            acc2[2 * d]     = ffma2(pe21, v1.x, acc2[2 * d]);
            acc2[2 * d + 1] = ffma2(pe21, v1.y, acc2[2 * d + 1]);
        }
    }
    {   // tail key j = 76
        const int j = LSEQ - 1;
        const ulonglong2* kj = (const ulonglong2*)(ks + j * 20 + half * 10);
        u64 sA = 0ULL, sB = 0ULL;
        #pragma unroll
        for (int d = 0; d < 5; ++d) {
            ulonglong2 kk = kj[d];
            sA = ffma2(q2[2 * d], kk.x, sA);
            sB = ffma2(q2[2 * d + 1], kk.y, sB);
        }
        float2 fa = unpk2(sA), fb = unpk2(sB);
        float part = (fa.x + fa.y) + (fb.x + fb.y);
        part += __shfl_xor_sync(umask, part, 1);
        float pe = __expf(part * scale);
        l += pe;
        u64 pe2 = pack2(pe, pe);
        const ulonglong2* vj = (const ulonglong2*)(vs + j * 20 + half * 10);
        #pragma unroll
        for (int d = 0; d < 5; ++d) {
            ulonglong2 vv = vj[d];
            acc2[2 * d]     = ffma2(pe2, vv.x, acc2[2 * d]);
            acc2[2 * d + 1] = ffma2(pe2, vv.y, acc2[2 * d + 1]);
        }
    }

    float inv = 1.f / l;
    float sc = (b == 0) ? inv : wg * inv;   // pre-weighted; reduce kernel just sums
    #pragma unroll
    for (int d = 0; d < 5; ++d) {
        float2 x = unpk2(acc2[2 * d]);
        float2 y = unpk2(acc2[2 * d + 1]);
        o4[d] = make_float4(x.x * sc, x.y * sc, y.x * sc, y.y * sc);
    }
}

// ---------------- sum the 9 pre-weighted batch outputs (w-aware) -----------
__global__ void __launch_bounds__(256) reduce9_kernel()
{
    int idx = blockIdx.x * 256 + threadIdx.x;   // over HW*CMODEL/4 float4s
    int p = idx / (CMODEL / 4);                 // pixel of this float4
    const float4* o4 = (const float4*)g_O;
    const size_t stride = (size_t)HW * CMODEL / 4;
    float4 s = make_float4(0.f, 0.f, 0.f, 0.f);
    #pragma unroll
    for (int bb = 0; bb < NPHASE; ++bb) {
        if (g_w9[bb * HW + p] != 0.f) {         // skip exactly-zero rows (~85%)
            float4 v = o4[bb * stride + idx];
            s.x += v.x; s.y += v.y; s.z += v.z; s.w += v.w;
        }
    }
    ((float4*)(g_A + (size_t)HW * CMODEL))[idx] = s;
}

// ---------------- launch ---------------------------------------------------
extern "C" void kernel_launch(void* const* d_in, const int* in_sizes, int n_in,
                              void* d_out, int out_size)
{
    (void)in_sizes; (void)n_in; (void)out_size;
    const float* hs  = (const float*)d_in[0];
    const float* ehs = (const float*)d_in[1];
    const float* bb  = (const float*)d_in[2];
    const float* Wq  = (const float*)d_in[3];
    const float* Wk  = (const float*)d_in[4];
    const float* Wv  = (const float*)d_in[5];
    const float* Wo  = (const float*)d_in[6];
    const float* bo  = (const float*)d_in[7];
    float* out = (float*)d_out;

    weights_kernel<<<16, 256>>>(bb);

    dim3 gblk(8, 16);    // 128 threads, 8x8 micro
    qproj_kernel<<<dim3(CMODEL / 64, (2 * HW) / 128), gblk>>>(hs, Wq);
    kvproj_kernel<<<dim3(CMODEL / 64, (NB * LSEQ + 31) / 32), dim3(16, 16)>>>(ehs, Wk, Wv);

    att_kernel<<<dim3(HW / 128, HEADS, NB), 256>>>();

    reduce9_kernel<<<(HW * CMODEL / 4) / 256, 256>>>();

    outproj_kernel<<<dim3(CMODEL / 64, (2 * HW) / 128), gblk>>>(Wo, bo, out);
}

// round 15
// speedup vs baseline: 1.7632x; 1.0032x over previous
#include <cuda_runtime.h>
#include <math.h>

#define HEADS 8
#define DHEAD 40
#define CMODEL 320
#define CX 768
#define LSEQ 77
#define NB 10
#define HW 4096
#define NPHASE 9

typedef unsigned long long u64;

// ---------------- packed f32x2 helpers (FFMA2 path, sm_100+) ---------------
__device__ __forceinline__ u64 pack2(float lo, float hi) {
    u64 r; asm("mov.b64 %0, {%1, %2};" : "=l"(r) : "f"(lo), "f"(hi)); return r;
}
__device__ __forceinline__ float2 unpk2(u64 v) {
    float2 f; asm("mov.b64 {%0, %1}, %2;" : "=f"(f.x), "=f"(f.y) : "l"(v)); return f;
}
__device__ __forceinline__ u64 ffma2(u64 a, u64 b, u64 c) {
    u64 d; asm("fma.rn.f32x2 %0, %1, %2, %3;" : "=l"(d) : "l"(a), "l"(b), "l"(c)); return d;
}

// ---------------- scratch (device globals; no allocation allowed) ----------
__device__ __align__(16) float g_q[2 * HW * CMODEL];
__device__ __align__(16) float g_k[NB * LSEQ * CMODEL];
__device__ __align__(16) float g_v[NB * LSEQ * CMODEL];
__device__ __align__(16) float g_A[2 * HW * CMODEL];      // [0:HW)=uncond, [HW:2HW)=weighted sum
__device__ __align__(16) float g_O[NPHASE * HW * CMODEL]; // per-batch weighted outputs (b=1..9)
__device__ __align__(16) float g_w9[NPHASE * HW];
__device__ __align__(16) float g_wsum[HW];

// ---------------- phase weights (jax.image.resize bilinear+antialias) ------
__device__ __forceinline__ float resize_factor(int o, float lo, float hi) {
    float sf = (o + 0.5f) * 8.0f - 0.5f;
    float num = 0.f, den = 0.f;
    int h0 = o * 8 - 4, h1 = o * 8 + 11;
    #pragma unroll 1
    for (int h = h0; h <= h1; ++h) {
        if (h < 0 || h > 511) continue;
        float fh = (float)h;
        float wgt = 1.0f - fabsf(fh - sf) * 0.125f;
        den += wgt;
        if (fh >= lo && fh < hi) num += wgt;
    }
    return num / den;
}

__global__ void weights_kernel(const float* __restrict__ bboxes) {
    int p = blockIdx.x * blockDim.x + threadIdx.x;
    if (p >= HW) return;
    int r = p >> 6, c = p & 63;
    float s = 0.1f;
    g_w9[p] = 0.1f;
    #pragma unroll 1
    for (int i = 0; i < 8; ++i) {
        float x0 = bboxes[i * 4 + 0], y0 = bboxes[i * 4 + 1];
        float x1 = bboxes[i * 4 + 2], y1 = bboxes[i * 4 + 3];
        float wmin = floorf(512.f * x0), wmax = floorf(512.f * x1);
        float hmin = floorf(512.f * y0), hmax = floorf(512.f * y1);
        float wv = 10.f * resize_factor(r, hmin, hmax) * resize_factor(c, wmin, wmax);
        g_w9[(i + 1) * HW + p] = wv;
        s += wv;
    }
    g_wsum[p] = s;
}

// ---------------- fused K+V projection: 32x64 tile (125 blocks) ------------
__global__ void __launch_bounds__(256) kvproj_kernel(
    const float* __restrict__ ehs,
    const float* __restrict__ Wk, const float* __restrict__ Wv)
{
    __shared__ __align__(16) float As[16][36];
    __shared__ __align__(16) float Bk[16][64];
    __shared__ __align__(16) float Bv[16][64];
    const int tx = threadIdx.x, ty = threadIdx.y;
    const int t  = ty * 16 + tx;
    const int row0 = blockIdx.y * 32, col0 = blockIdx.x * 64;
    const int li = t >> 3, lk = (t & 7) << 1;    // A: 32 rows x 16 k, float2 each
    const int bk = t >> 4, bj = (t & 15) << 2;

    u64 ak[4], av[4];
    #pragma unroll
    for (int j = 0; j < 4; ++j) { ak[j] = 0ULL; av[j] = 0ULL; }

    for (int k0 = 0; k0 < CX; k0 += 16) {
        // rows up to 799 < 847 total in ehs — unguarded load is safe
        float2 a = *(const float2*)(ehs + (size_t)(row0 + li) * CX + k0 + lk);
        As[lk + 0][li] = a.x; As[lk + 1][li] = a.y;
        *(float4*)(&Bk[bk][bj]) = *(const float4*)(Wk + (size_t)(k0 + bk) * CMODEL + col0 + bj);
        *(float4*)(&Bv[bk][bj]) = *(const float4*)(Wv + (size_t)(k0 + bk) * CMODEL + col0 + bj);
        __syncthreads();
        #pragma unroll
        for (int kk = 0; kk < 16; ++kk) {
            u64 ap = *(const u64*)(&As[kk][ty * 2]);   // row pair (2ty, 2ty+1)
            float4 b1 = *(const float4*)(&Bk[kk][tx * 4]);
            float4 b2 = *(const float4*)(&Bv[kk][tx * 4]);
            ak[0] = ffma2(ap, pack2(b1.x, b1.x), ak[0]);
            ak[1] = ffma2(ap, pack2(b1.y, b1.y), ak[1]);
            ak[2] = ffma2(ap, pack2(b1.z, b1.z), ak[2]);
            ak[3] = ffma2(ap, pack2(b1.w, b1.w), ak[3]);
            av[0] = ffma2(ap, pack2(b2.x, b2.x), av[0]);
            av[1] = ffma2(ap, pack2(b2.y, b2.y), av[1]);
            av[2] = ffma2(ap, pack2(b2.z, b2.z), av[2]);
            av[3] = ffma2(ap, pack2(b2.w, b2.w), av[3]);
        }
        __syncthreads();
    }
    float2 c0 = unpk2(ak[0]), c1 = unpk2(ak[1]), c2 = unpk2(ak[2]), c3 = unpk2(ak[3]);
    float2 d0 = unpk2(av[0]), d1 = unpk2(av[1]), d2 = unpk2(av[2]), d3 = unpk2(av[3]);
    int re = row0 + ty * 2;
    if (re < NB * LSEQ) {
        *(float4*)(g_k + (size_t)re * CMODEL + col0 + tx * 4) = make_float4(c0.x, c1.x, c2.x, c3.x);
        *(float4*)(g_v + (size_t)re * CMODEL + col0 + tx * 4) = make_float4(d0.x, d1.x, d2.x, d3.x);
    }
    if (re + 1 < NB * LSEQ) {
        *(float4*)(g_k + (size_t)(re + 1) * CMODEL + col0 + tx * 4) = make_float4(c0.y, c1.y, c2.y, c3.y);
        *(float4*)(g_v + (size_t)(re + 1) * CMODEL + col0 + tx * 4) = make_float4(d0.y, d1.y, d2.y, d3.y);
    }
}

// ---------------- 128x64 GEMM core, 8x8 micro, double-buffered smem --------
__device__ __forceinline__ void gemm128_f2(
    const float* __restrict__ A, const float* __restrict__ B,
    int K, int N, u64 (&acc)[4][8])
{
    __shared__ __align__(16) float As[2][16][132];
    __shared__ __align__(16) float Bs[2][16][64];
    const int tx = threadIdx.x, ty = threadIdx.y;   // tx 0..7, ty 0..15
    const int t  = ty * 8 + tx;                     // 0..127
    const int row0 = blockIdx.y * 128, col0 = blockIdx.x * 64;
    const int bk = t >> 3, bj = (t & 7) << 3;       // B: 16 k-rows x 64 cols, 8 floats/thr

    #pragma unroll
    for (int i = 0; i < 4; ++i)
        #pragma unroll
        for (int j = 0; j < 8; ++j) acc[i][j] = 0ULL;

    const float* apg = A + (size_t)(row0 + t) * K;
    const float* bpg = B + (size_t)bk * N + col0 + bj;

    // stage tile 0 into buffer 0
    {
        #pragma unroll
        for (int j = 0; j < 4; ++j) {
            float4 a = *(const float4*)(apg + 4 * j);
            As[0][4 * j + 0][t] = a.x; As[0][4 * j + 1][t] = a.y;
            As[0][4 * j + 2][t] = a.z; As[0][4 * j + 3][t] = a.w;
        }
        *(float4*)(&Bs[0][bk][bj])     = *(const float4*)(bpg);
        *(float4*)(&Bs[0][bk][bj + 4]) = *(const float4*)(bpg + 4);
    }
    __syncthreads();

    int cur = 0;
    for (int k0 = 0; k0 < K; k0 += 16) {
        // prefetch next tile into regs (overlaps the compute below)
        float4 ar[4]; float4 br0, br1;
        const bool more = (k0 + 16 < K);
        if (more) {
            #pragma unroll
            for (int j = 0; j < 4; ++j) ar[j] = *(const float4*)(apg + k0 + 16 + 4 * j);
            br0 = *(const float4*)(bpg + (size_t)(k0 + 16) * N);
            br1 = *(const float4*)(bpg + (size_t)(k0 + 16) * N + 4);
        }

        #pragma unroll
        for (int kk = 0; kk < 16; ++kk) {
            const ulonglong2* arow = (const ulonglong2*)(&As[cur][kk][ty * 8]);
            ulonglong2 aA = arow[0], aB = arow[1];   // row pairs (0,1),(2,3),(4,5),(6,7)
            float4 blo = *(const float4*)(&Bs[cur][kk][tx * 4]);
            float4 bhi = *(const float4*)(&Bs[cur][kk][32 + tx * 4]);
            u64 s0 = pack2(blo.x, blo.x), s1 = pack2(blo.y, blo.y);
            u64 s2 = pack2(blo.z, blo.z), s3 = pack2(blo.w, blo.w);
            u64 s4 = pack2(bhi.x, bhi.x), s5 = pack2(bhi.y, bhi.y);
            u64 s6 = pack2(bhi.z, bhi.z), s7 = pack2(bhi.w, bhi.w);
            acc[0][0] = ffma2(aA.x, s0, acc[0][0]); acc[0][1] = ffma2(aA.x, s1, acc[0][1]);
            acc[0][2] = ffma2(aA.x, s2, acc[0][2]); acc[0][3] = ffma2(aA.x, s3, acc[0][3]);
            acc[0][4] = ffma2(aA.x, s4, acc[0][4]); acc[0][5] = ffma2(aA.x, s5, acc[0][5]);
            acc[0][6] = ffma2(aA.x, s6, acc[0][6]); acc[0][7] = ffma2(aA.x, s7, acc[0][7]);
            acc[1][0] = ffma2(aA.y, s0, acc[1][0]); acc[1][1] = ffma2(aA.y, s1, acc[1][1]);
            acc[1][2] = ffma2(aA.y, s2, acc[1][2]); acc[1][3] = ffma2(aA.y, s3, acc[1][3]);
            acc[1][4] = ffma2(aA.y, s4, acc[1][4]); acc[1][5] = ffma2(aA.y, s5, acc[1][5]);
            acc[1][6] = ffma2(aA.y, s6, acc[1][6]); acc[1][7] = ffma2(aA.y, s7, acc[1][7]);
            acc[2][0] = ffma2(aB.x, s0, acc[2][0]); acc[2][1] = ffma2(aB.x, s1, acc[2][1]);
            acc[2][2] = ffma2(aB.x, s2, acc[2][2]); acc[2][3] = ffma2(aB.x, s3, acc[2][3]);
            acc[2][4] = ffma2(aB.x, s4, acc[2][4]); acc[2][5] = ffma2(aB.x, s5, acc[2][5]);
            acc[2][6] = ffma2(aB.x, s6, acc[2][6]); acc[2][7] = ffma2(aB.x, s7, acc[2][7]);
            acc[3][0] = ffma2(aB.y, s0, acc[3][0]); acc[3][1] = ffma2(aB.y, s1, acc[3][1]);
            acc[3][2] = ffma2(aB.y, s2, acc[3][2]); acc[3][3] = ffma2(aB.y, s3, acc[3][3]);
            acc[3][4] = ffma2(aB.y, s4, acc[3][4]); acc[3][5] = ffma2(aB.y, s5, acc[3][5]);
            acc[3][6] = ffma2(aB.y, s6, acc[3][6]); acc[3][7] = ffma2(aB.y, s7, acc[3][7]);
        }

        if (more) {
            int nxt = cur ^ 1;
            #pragma unroll
            for (int j = 0; j < 4; ++j) {
                As[nxt][4 * j + 0][t] = ar[j].x; As[nxt][4 * j + 1][t] = ar[j].y;
                As[nxt][4 * j + 2][t] = ar[j].z; As[nxt][4 * j + 3][t] = ar[j].w;
            }
            *(float4*)(&Bs[nxt][bk][bj])     = br0;
            *(float4*)(&Bs[nxt][bk][bj + 4]) = br1;
            __syncthreads();
            cur = nxt;
        }
    }
}

// Q projection: [8192,320] x [320,320] -> g_q
__global__ void __launch_bounds__(128) qproj_kernel(
    const float* __restrict__ hs, const float* __restrict__ Wq)
{
    u64 acc[4][8];
    gemm128_f2(hs, Wq, CMODEL, CMODEL, acc);
    const int row0 = blockIdx.y * 128, col0 = blockIdx.x * 64;
    const int tx = threadIdx.x, ty = threadIdx.y;
    #pragma unroll
    for (int i = 0; i < 4; ++i) {
        float2 p[8];
        #pragma unroll
        for (int j = 0; j < 8; ++j) p[j] = unpk2(acc[i][j]);
        int re = row0 + ty * 8 + 2 * i;
        float* r0 = g_q + (size_t)re * CMODEL + col0;
        float* r1 = r0 + CMODEL;
        *(float4*)(r0 + tx * 4)      = make_float4(p[0].x, p[1].x, p[2].x, p[3].x);
        *(float4*)(r0 + 32 + tx * 4) = make_float4(p[4].x, p[5].x, p[6].x, p[7].x);
        *(float4*)(r1 + tx * 4)      = make_float4(p[0].y, p[1].y, p[2].y, p[3].y);
        *(float4*)(r1 + 32 + tx * 4) = make_float4(p[4].y, p[5].y, p[6].y, p[7].y);
    }
}

// Output projection + fused epilogue
__global__ void __launch_bounds__(128) outproj_kernel(
    const float* __restrict__ Wo, const float* __restrict__ bo,
    float* __restrict__ out)
{
    u64 acc[4][8];
    gemm128_f2(g_A, Wo, CMODEL, CMODEL, acc);
    const int row0 = blockIdx.y * 128, col0 = blockIdx.x * 64;
    const int tx = threadIdx.x, ty = threadIdx.y;
    const int cA = col0 + tx * 4, cB = col0 + 32 + tx * 4;
    float4 bA = *(const float4*)(bo + cA);
    float4 bB = *(const float4*)(bo + cB);
    #pragma unroll
    for (int i = 0; i < 4; ++i) {
        float2 p[8];
        #pragma unroll
        for (int j = 0; j < 8; ++j) p[j] = unpk2(acc[i][j]);
        #pragma unroll
        for (int h = 0; h < 2; ++h) {
            int r = row0 + ty * 8 + 2 * i + h;
            float v0 = h ? p[0].y : p[0].x, v1 = h ? p[1].y : p[1].x;
            float v2 = h ? p[2].y : p[2].x, v3 = h ? p[3].y : p[3].x;
            float v4 = h ? p[4].y : p[4].x, v5 = h ? p[5].y : p[5].x;
            float v6 = h ? p[6].y : p[6].x, v7 = h ? p[7].y : p[7].x;
            float4 oA, oB;
            if (r < HW) {
                oA = make_float4(v0 + bA.x, v1 + bA.y, v2 + bA.z, v3 + bA.w);
                oB = make_float4(v4 + bB.x, v5 + bB.y, v6 + bB.z, v7 + bB.w);
            } else {
                float ws = g_wsum[r - HW];
                float invD = 1.f / (ws + 1e-6f);
                float bs = ws * invD;
                oA = make_float4(v0 * invD + bA.x * bs, v1 * invD + bA.y * bs,
                                 v2 * invD + bA.z * bs, v3 * invD + bA.w * bs);
                oB = make_float4(v4 * invD + bB.x * bs, v5 * invD + bB.y * bs,
                                 v6 * invD + bB.z * bs, v7 * invD + bB.w * bs);
            }
            *(float4*)(out + (size_t)r * CMODEL + cA) = oA;
            *(float4*)(out + (size_t)r * CMODEL + cB) = oB;
        }
    }
}

// ---------------- attention: thread-pair handles TWO adjacent pixels -------
// Block covers 256 pixels; lanes (2i,2i+1) split head dims for pixels
// (2i, 2i+1). K/V smem loads are shared across both pixels (half the LDS
// per FMA); two independent pixel chains hide SHFL+MUFU latency.
__global__ void __launch_bounds__(256) att_kernel()
{
    __shared__ __align__(16) u64 ks[LSEQ * 20];   // 77 rows x 40 floats (20 u64)
    __shared__ __align__(16) u64 vs[LSEQ * 20];
    const int head = blockIdx.y;
    const int b = blockIdx.z;
    const int t = threadIdx.x;        // 0..255
    const int pl = t >> 1;            // pair 0..127
    const int half = t & 1;           // dim half: floats [half*20, half*20+20)
    const int p0 = blockIdx.x * 256 + pl * 2;
    const int p1 = p0 + 1;
    const float scale = 0.15811388300841897f;     // 1/sqrt(40)

    float wg0 = 1.f, wg1 = 1.f;
    float *optr0, *optr1;
    if (b == 0) {
        optr0 = g_A + (size_t)p0 * CMODEL + head * DHEAD;
        optr1 = g_A + (size_t)p1 * CMODEL + head * DHEAD;
    } else {
        wg0 = g_w9[(b - 1) * HW + p0];
        wg1 = g_w9[(b - 1) * HW + p1];
        optr0 = g_O + ((size_t)(b - 1) * HW + p0) * CMODEL + head * DHEAD;
        optr1 = g_O + ((size_t)(b - 1) * HW + p1) * CMODEL + head * DHEAD;
    }

    // whole-block skip (bbox rectangles cover ~15% of pixels for b>=2)
    int any = __syncthreads_count((wg0 != 0.f) || (wg1 != 0.f));
    if (any == 0) return;

    // stage K/V head tile (16B vectors; CMODEL row = 80 ulonglong2)
    {
        const ulonglong2* gk = (const ulonglong2*)g_k;
        const ulonglong2* gv = (const ulonglong2*)g_v;
        ulonglong2* ks2 = (ulonglong2*)ks;
        ulonglong2* vs2 = (ulonglong2*)vs;
        for (int idx = t; idx < LSEQ * 10; idx += 256) {
            int j = idx / 10, d = idx - j * 10;
            int g = (b * LSEQ + j) * 80 + head * 10 + d;
            ks2[idx] = gk[g];
            vs2[idx] = gv[g];
        }
    }
    __syncthreads();

    // per-pair skip (pair-uniform: both lanes share wg0,wg1)
    if (wg0 == 0.f && wg1 == 0.f) return;
    unsigned umask = __activemask();

    // load both pixels' 20-float halves (5 ulonglong2 each)
    const int qb = (b == 0) ? 0 : 1;
    u64 qa[10], qc[10];
    {
        const ulonglong2* qp0 = (const ulonglong2*)(
            g_q + ((size_t)qb * HW + p0) * CMODEL + head * DHEAD + half * 20);
        const ulonglong2* qp1 = (const ulonglong2*)(
            g_q + ((size_t)qb * HW + p1) * CMODEL + head * DHEAD + half * 20);
        #pragma unroll
        for (int d = 0; d < 5; ++d) {
            ulonglong2 qq0 = qp0[d], qq1 = qp1[d];
            qa[2 * d] = qq0.x; qa[2 * d + 1] = qq0.y;
            qc[2 * d] = qq1.x; qc[2 * d + 1] = qq1.y;
        }
    }

    u64 acc0[10], acc1[10];
    #pragma unroll
    for (int d = 0; d < 10; ++d) { acc0[d] = 0ULL; acc1[d] = 0ULL; }
    float l0 = 0.f, l1 = 0.f;

    // single-pass softmax (no max subtraction: |scores| <~ 1.5, safe in fp32)
    #pragma unroll 1
    for (int j = 0; j < LSEQ; ++j) {
        const ulonglong2* kj = (const ulonglong2*)(ks + j * 20 + half * 10);
        u64 sA0 = 0ULL, sB0 = 0ULL, sA1 = 0ULL, sB1 = 0ULL;
        #pragma unroll
        for (int d = 0; d < 5; ++d) {
            ulonglong2 kk = kj[d];
            sA0 = ffma2(qa[2 * d], kk.x, sA0); sB0 = ffma2(qa[2 * d + 1], kk.y, sB0);
            sA1 = ffma2(qc[2 * d], kk.x, sA1); sB1 = ffma2(qc[2 * d + 1], kk.y, sB1);
        }
        float2 fa0 = unpk2(sA0), fb0 = unpk2(sB0);
        float2 fa1 = unpk2(sA1), fb1 = unpk2(sB1);
        float part0 = (fa0.x + fa0.y) + (fb0.x + fb0.y);
        float part1 = (fa1.x + fa1.y) + (fb1.x + fb1.y);
        part0 += __shfl_xor_sync(umask, part0, 1);
        part1 += __shfl_xor_sync(umask, part1, 1);
        float pe0 = __expf(part0 * scale);
        float pe1 = __expf(part1 * scale);
        l0 += pe0; l1 += pe1;
        u64 pe20 = pack2(pe0, pe0), pe21 = pack2(pe1, pe1);
        const ulonglong2* vj = (const ulonglong2*)(vs + j * 20 + half * 10);
        #pragma unroll
        for (int d = 0; d < 5; ++d) {
            ulonglong2 vv = vj[d];
            acc0[2 * d]     = ffma2(pe20, vv.x, acc0[2 * d]);
            acc0[2 * d + 1] = ffma2(pe20, vv.y, acc0[2 * d + 1]);
            acc1[2 * d]     = ffma2(pe21, vv.x, acc1[2 * d]);
            acc1[2 * d + 1] = ffma2(pe21, vv.y, acc1[2 * d + 1]);
        }
    }

    // store pixel 0 (skip zero-weight rows; reduce9 never reads them)
    if (wg0 != 0.f) {
        float sc = (b == 0) ? (1.f / l0) : (wg0 / l0);
        float4* o4 = (float4*)(optr0 + half * 20);
        #pragma unroll
        for (int d = 0; d < 5; ++d) {
            float2 x = unpk2(acc0[2 * d]);
            float2 y = unpk2(acc0[2 * d + 1]);
            o4[d] = make_float4(x.x * sc, x.y * sc, y.x * sc, y.y * sc);
        }
    }
    if (wg1 != 0.f) {
        float sc = (b == 0) ? (1.f / l1) : (wg1 / l1);
        float4* o4 = (float4*)(optr1 + half * 20);
        #pragma unroll
        for (int d = 0; d < 5; ++d) {
            float2 x = unpk2(acc1[2 * d]);
            float2 y = unpk2(acc1[2 * d + 1]);
            o4[d] = make_float4(x.x * sc, x.y * sc, y.x * sc, y.y * sc);
        }
    }
}

// ---------------- sum the 9 pre-weighted batch outputs (w-aware) -----------
__global__ void __launch_bounds__(256) reduce9_kernel()
{
    int idx = blockIdx.x * 256 + threadIdx.x;   // over HW*CMODEL/4 float4s
    int p = idx / (CMODEL / 4);                 // pixel of this float4
    const float4* o4 = (const float4*)g_O;
    const size_t stride = (size_t)HW * CMODEL / 4;
    float4 s = make_float4(0.f, 0.f, 0.f, 0.f);
    #pragma unroll
    for (int bb = 0; bb < NPHASE; ++bb) {
        if (g_w9[bb * HW + p] != 0.f) {         // skip exactly-zero rows (~85%)
            float4 v = o4[bb * stride + idx];
            s.x += v.x; s.y += v.y; s.z += v.z; s.w += v.w;
        }
    }
    ((float4*)(g_A + (size_t)HW * CMODEL))[idx] = s;
}

// ---------------- launch ---------------------------------------------------
extern "C" void kernel_launch(void* const* d_in, const int* in_sizes, int n_in,
                              void* d_out, int out_size)
{
    (void)in_sizes; (void)n_in; (void)out_size;
    const float* hs  = (const float*)d_in[0];
    const float* ehs = (const float*)d_in[1];
    const float* bb  = (const float*)d_in[2];
    const float* Wq  = (const float*)d_in[3];
    const float* Wk  = (const float*)d_in[4];
    const float* Wv  = (const float*)d_in[5];
    const float* Wo  = (const float*)d_in[6];
    const float* bo  = (const float*)d_in[7];
    float* out = (float*)d_out;

    weights_kernel<<<16, 256>>>(bb);

    dim3 gblk(8, 16);    // 128 threads, 8x8 micro
    qproj_kernel<<<dim3(CMODEL / 64, (2 * HW) / 128), gblk>>>(hs, Wq);
    kvproj_kernel<<<dim3(CMODEL / 64, (NB * LSEQ + 31) / 32), dim3(16, 16)>>>(ehs, Wk, Wv);

    att_kernel<<<dim3(HW / 256, HEADS, NB), 256>>>();

    reduce9_kernel<<<(HW * CMODEL / 4) / 256, 256>>>();

    outproj_kernel<<<dim3(CMODEL / 64, (2 * HW) / 128), gblk>>>(Wo, bo, out);
}